// round 5
// baseline (speedup 1.0000x reference)
#include <cuda_runtime.h>

#define NN 100000
#define NE 1000000
#define DD 64
#define NG 128
#define NL 3
#define BN_EPS 1e-5f

// ---------------- scratch (device globals; no runtime alloc) ----------------
__device__ float  g_bufA[NN * DD];     // lin output t
__device__ float  g_bufB[NN * DD];     // node state: agg -> g (next layer input)
__device__ double g_stats[2 * DD];     // per-feature sum, sumsq (of g)
__device__ float  g_segsum[NG * DD];   // per-graph sums of g
__device__ int    g_cnt[NG];           // nodes per graph
__device__ float  g_Wt[DD * DD];       // folded, TRANSPOSED weight: Wt[k*64+j]
__device__ float  g_c[DD];             // folded constant added to lin output
__device__ int    g_idx64;             // 1 if index buffers are int64, 0 if int32

__device__ __forceinline__ int clampi(int v, int lim) {
    return v < 0 ? 0 : (v >= lim ? lim - 1 : v);
}

// read index i from a buffer that is either int64 or int32 (clamped to [0,lim))
__device__ __forceinline__ int ld_idx(const void* p, long long i, int is64, int lim) {
    int v = is64 ? (int)((const long long*)p)[i] : ((const int*)p)[i];
    return clampi(v, lim);
}

// ---------------- prologue: detect dtype, transpose W0, zero, graph counts ---
__global__ void __launch_bounds__(256) k_prep(const float* __restrict__ W,
                                              const void* __restrict__ ei,
                                              const void* __restrict__ batch) {
    int t = threadIdx.x;
    if (t == 0) {
        // int64 small nonneg values have zero high words at odd int32 positions.
        // Require agreement across 64 odd words of ei AND 64 odd words of batch.
        const int* w1 = (const int*)ei;
        const int* w2 = (const int*)batch;
        int allz = 1;
        for (int i = 1; i < 128; i += 2) allz &= (w1[i] == 0);
        for (int i = 1; i < 128; i += 2) allz &= (w2[i] == 0);
        g_idx64 = allz;
    }
    __syncthreads();
    int is64 = g_idx64;

    for (int idx = t; idx < DD * DD; idx += 256) {
        int j = idx >> 6, k = idx & 63;
        g_Wt[k * DD + j] = W[j * DD + k];          // layer 0: s = 1
    }
    for (int idx = t; idx < DD; idx += 256) g_c[idx] = 0.f;
    for (int idx = t; idx < 2 * DD; idx += 256) g_stats[idx] = 0.0;
    for (int idx = t; idx < NG * DD; idx += 256) g_segsum[idx] = 0.f;
    if (t < NG) {
        // lower_bound(t) and lower_bound(t+1) on sorted batch (raw, unclamped ok)
        int lo = 0, hi = NN;
        while (lo < hi) {
            int m = (lo + hi) >> 1;
            int v = is64 ? (int)((const long long*)batch)[m] : ((const int*)batch)[m];
            if (v < t) lo = m + 1; else hi = m;
        }
        int a = lo;
        lo = 0; hi = NN;
        while (lo < hi) {
            int m = (lo + hi) >> 1;
            int v = is64 ? (int)((const long long*)batch)[m] : ((const int*)batch)[m];
            if (v < t + 1) lo = m + 1; else hi = m;
        }
        g_cnt[t] = lo - a;
    }
}

// ---------------- lin: t = in @ Wt (+c), and seed agg buffer with bias -------
// block = 256 threads, 64 node rows per block. W tile + A tile in smem.
__global__ void __launch_bounds__(256) k_lin(const float* __restrict__ xin, int use_ext,
                                             const float* __restrict__ bias) {
    __shared__ __align__(16) float sA[64][64];
    __shared__ __align__(16) float sW[64][64];   // sW[k][j]
    int t = threadIdx.x;
    int base = blockIdx.x * 64;

    for (int idx = t; idx < DD * DD; idx += 256) sW[idx >> 6][idx & 63] = g_Wt[idx];
    for (int idx = t; idx < 64 * DD; idx += 256) {
        int r = idx >> 6, k = idx & 63;
        int n = base + r;
        float v = 0.f;
        if (n < NN) v = use_ext ? xin[n * DD + k] : g_bufB[n * DD + k];
        sA[r][k] = v;
    }
    __syncthreads();

    int jg = t & 15;        // feature group (4 feats)
    int ns = (t >> 4) * 4;  // first of 4 node rows

    float4 cv = *(const float4*)&g_c[jg * 4];
    float4 acc0 = cv, acc1 = cv, acc2 = cv, acc3 = cv;

#pragma unroll 8
    for (int k = 0; k < DD; k++) {
        float4 wv = *(const float4*)&sW[k][jg * 4];
        float a0 = sA[ns + 0][k];
        float a1 = sA[ns + 1][k];
        float a2 = sA[ns + 2][k];
        float a3 = sA[ns + 3][k];
        acc0.x += a0 * wv.x; acc0.y += a0 * wv.y; acc0.z += a0 * wv.z; acc0.w += a0 * wv.w;
        acc1.x += a1 * wv.x; acc1.y += a1 * wv.y; acc1.z += a1 * wv.z; acc1.w += a1 * wv.w;
        acc2.x += a2 * wv.x; acc2.y += a2 * wv.y; acc2.z += a2 * wv.z; acc2.w += a2 * wv.w;
        acc3.x += a3 * wv.x; acc3.y += a3 * wv.y; acc3.z += a3 * wv.z; acc3.w += a3 * wv.w;
    }

    float4 bv = *(const float4*)&bias[jg * 4];
    float4 accs[4] = {acc0, acc1, acc2, acc3};
#pragma unroll
    for (int i = 0; i < 4; i++) {
        int n = base + ns + i;
        if (n < NN) {
            *(float4*)&g_bufA[n * DD + jg * 4] = accs[i];   // lin output (no bias)
            *(float4*)&g_bufB[n * DD + jg * 4] = bv;        // seed agg with conv bias
        }
    }
}

// ---------------- scatter: agg[dst] += w * t[src], 16 threads / edge ---------
__global__ void __launch_bounds__(256) k_scatter(const void* __restrict__ ei,
                                                 const float* __restrict__ ew) {
    int tid = blockIdx.x * 256 + threadIdx.x;
    int e = tid >> 4;
    if (e >= NE) return;
    int jg = tid & 15;
    int is64 = g_idx64;

    // all 16 threads of an edge read the same scalars -> L1 broadcast
    int   s = ld_idx(ei, e, is64, NN);
    int   d = ld_idx(ei, (long long)NE + e, is64, NN);
    float w = ew[e];

    float4 v = *(const float4*)&g_bufA[s * DD + jg * 4];
    float* p = &g_bufB[d * DD + jg * 4];
    atomicAdd(p + 0, v.x * w);
    atomicAdd(p + 1, v.y * w);
    atomicAdd(p + 2, v.z * w);
    atomicAdd(p + 3, v.w * w);
}

// ---------------- stats: g = prelu(agg) in-place; BN stats; graph segsum -----
// grid 782 blocks * 128 nodes; thread: jg = t&15, slot = t>>4, 8 nodes strided.
__global__ void __launch_bounds__(256) k_stats(const void* __restrict__ batch,
                                               const float* __restrict__ prelu_a) {
    __shared__ double sred[16][16][8];   // [slot][jg][sum0..3, sq0..3] = 16 KB
    int t = threadIdx.x;
    int jg = t & 15, slot = t >> 4;
    float a = prelu_a[0];
    int base = blockIdx.x * 128;
    int is64 = g_idx64;

    double s0 = 0, s1 = 0, s2 = 0, s3 = 0, q0 = 0, q1 = 0, q2 = 0, q3 = 0;

#pragma unroll
    for (int i = 0; i < 8; i++) {
        int n = base + i * 16 + slot;
        if (n < NN) {
            int bg = ld_idx(batch, n, is64, NG);   // 16 threads broadcast-load
            float4 v = *(const float4*)&g_bufB[n * DD + jg * 4];
            v.x = v.x >= 0.f ? v.x : a * v.x;
            v.y = v.y >= 0.f ? v.y : a * v.y;
            v.z = v.z >= 0.f ? v.z : a * v.z;
            v.w = v.w >= 0.f ? v.w : a * v.w;
            *(float4*)&g_bufB[n * DD + jg * 4] = v;
            s0 += v.x; s1 += v.y; s2 += v.z; s3 += v.w;
            q0 += (double)v.x * v.x; q1 += (double)v.y * v.y;
            q2 += (double)v.z * v.z; q3 += (double)v.w * v.w;
            float* p = &g_segsum[bg * DD + jg * 4];
            atomicAdd(p + 0, v.x);
            atomicAdd(p + 1, v.y);
            atomicAdd(p + 2, v.z);
            atomicAdd(p + 3, v.w);
        }
    }

    sred[slot][jg][0] = s0; sred[slot][jg][1] = s1;
    sred[slot][jg][2] = s2; sred[slot][jg][3] = s3;
    sred[slot][jg][4] = q0; sred[slot][jg][5] = q1;
    sred[slot][jg][6] = q2; sred[slot][jg][7] = q3;
    __syncthreads();
    for (int off = 8; off > 0; off >>= 1) {
        if (slot < off) {
#pragma unroll
            for (int m = 0; m < 8; m++) sred[slot][jg][m] += sred[slot + off][jg][m];
        }
        __syncthreads();
    }
    if (slot == 0) {
#pragma unroll
        for (int m = 0; m < 4; m++) {
            atomicAdd(&g_stats[jg * 4 + m], sred[0][jg][m]);
            atomicAdd(&g_stats[DD + jg * 4 + m], sred[0][jg][4 + m]);
        }
    }
}

// ---------------- epilogue: BN params, pooled outputs, fold next W -----------
__global__ void __launch_bounds__(256) k_epi(const float* __restrict__ W,
                                             const float* __restrict__ bnw,
                                             const float* __restrict__ bnb,
                                             float* __restrict__ outp, int layer) {
    __shared__ float ss[DD], sh[DD];
    int t = threadIdx.x;
    if (t < DD) {
        double n = (double)NN;
        double mean = g_stats[t] / n;
        double var = g_stats[DD + t] / n - mean * mean;
        float istd = rsqrtf((float)var + BN_EPS);
        float s = istd * bnw[layer * DD + t];
        float shift = bnb[layer * DD + t] - (float)mean * s;
        ss[t] = s; sh[t] = shift;
        g_stats[t] = 0.0; g_stats[DD + t] = 0.0;   // re-zero for next layer
    }
    __syncthreads();

    // pooled[g, j] = segsum[g, j] * s[j] + cnt[g] * shift[j]
    for (int idx = t; idx < NG * DD; idx += 256) {
        int g = idx >> 6, j = idx & 63;
        float val = g_segsum[idx] * ss[j] + (float)g_cnt[g] * sh[j];
        g_segsum[idx] = 0.f;                       // re-zero for next layer
        outp[g * (NL * DD) + layer * DD + j] = val;
        if (layer == NL - 1) outp[NG * NL * DD + g * DD + j] = val;  // x_stack
    }

    // fold BN into next layer's weight (transposed) and constant
    if (layer < NL - 1) {
        const float* Wn = W + (layer + 1) * DD * DD;
        for (int idx = t; idx < DD * DD; idx += 256) {
            int j = idx >> 6, k = idx & 63;
            g_Wt[k * DD + j] = ss[k] * Wn[j * DD + k];
        }
        if (t < DD) {
            float c = 0.f;
#pragma unroll
            for (int k = 0; k < DD; k++) c += sh[k] * Wn[t * DD + k];
            g_c[t] = c;
        }
    }
}

// ---------------- driver ----------------
extern "C" void kernel_launch(void* const* d_in, const int* in_sizes, int n_in,
                              void* d_out, int out_size) {
    const float* x     = (const float*)d_in[0];
    const void*  ei    = d_in[1];
    const float* ea    = (const float*)d_in[2];
    const void*  batch = d_in[3];
    const float* W     = (const float*)d_in[4];
    const float* b     = (const float*)d_in[5];
    const float* pa    = (const float*)d_in[6];
    const float* bnw   = (const float*)d_in[7];
    const float* bnb   = (const float*)d_in[8];
    float* outp = (float*)d_out;

    k_prep<<<1, 256>>>(W, ei, batch);
    for (int L = 0; L < NL; L++) {
        k_lin<<<(NN + 63) / 64, 256>>>(x, L == 0 ? 1 : 0, b + L * DD);
        k_scatter<<<(NE * 16 + 255) / 256, 256>>>(ei, ea);
        k_stats<<<(NN + 127) / 128, 256>>>(batch, pa);
        k_epi<<<1, 256>>>(W, bnw, bnb, outp, L);
    }
}

// round 8
// speedup vs baseline: 1.2662x; 1.2662x over previous
#include <cuda_runtime.h>

#define NN 100000
#define NE 1000000
#define DD 64
#define NG 128
#define NL 3
#define BN_EPS 1e-5f

// ---------------- scratch (device globals; no runtime alloc) ----------------
__device__ __align__(16) float  g_bufA[NN * DD];   // lin output t
__device__ __align__(16) float  g_bufB[NN * DD];   // node state: agg -> g
__device__ double g_stats[DD];                     // per-feature sumsq of g
__device__ __align__(16) float  g_segsum[NG * DD]; // per-graph sums of g
__device__ int    g_cnt[NG];                       // nodes per graph
__device__ float  g_Wt[DD * DD];                   // folded, TRANSPOSED weight
__device__ float  g_c[DD];                         // folded constant
__device__ int    g_idx64;                         // 1 if int64 indices, 0 if int32

__device__ __forceinline__ int clampi(int v, int lim) {
    return v < 0 ? 0 : (v >= lim ? lim - 1 : v);
}

__device__ __forceinline__ int ld_idx(const void* p, long long i, int is64, int lim) {
    int v = is64 ? (int)((const long long*)p)[i] : ((const int*)p)[i];
    return clampi(v, lim);
}

// ---------------- prologue: detect dtype, transpose W0, zero, graph counts ---
__global__ void __launch_bounds__(256) k_prep(const float* __restrict__ W,
                                              const void* __restrict__ ei,
                                              const void* __restrict__ batch) {
    int t = threadIdx.x;
    if (t == 0) {
        const int* w1 = (const int*)ei;
        const int* w2 = (const int*)batch;
        int allz = 1;
        for (int i = 1; i < 128; i += 2) allz &= (w1[i] == 0);
        for (int i = 1; i < 128; i += 2) allz &= (w2[i] == 0);
        g_idx64 = allz;
    }
    __syncthreads();
    int is64 = g_idx64;

    for (int idx = t; idx < DD * DD; idx += 256) {
        int j = idx >> 6, k = idx & 63;
        g_Wt[k * DD + j] = W[j * DD + k];          // layer 0: s = 1
    }
    for (int idx = t; idx < DD; idx += 256) { g_c[idx] = 0.f; g_stats[idx] = 0.0; }
    for (int idx = t; idx < NG * DD; idx += 256) g_segsum[idx] = 0.f;
    if (t < NG) {
        int lo = 0, hi = NN;
        while (lo < hi) {
            int m = (lo + hi) >> 1;
            int v = is64 ? (int)((const long long*)batch)[m] : ((const int*)batch)[m];
            if (v < t) lo = m + 1; else hi = m;
        }
        int a = lo;
        lo = 0; hi = NN;
        while (lo < hi) {
            int m = (lo + hi) >> 1;
            int v = is64 ? (int)((const long long*)batch)[m] : ((const int*)batch)[m];
            if (v < t + 1) lo = m + 1; else hi = m;
        }
        g_cnt[t] = lo - a;
    }
}

// ---------------- lin: t = in @ Wt (+c), and seed agg buffer with bias -------
__global__ void __launch_bounds__(256) k_lin(const float* __restrict__ xin, int use_ext,
                                             const float* __restrict__ bias) {
    __shared__ __align__(16) float sA[64][64];
    __shared__ __align__(16) float sW[64][64];   // sW[k][j]
    int t = threadIdx.x;
    int base = blockIdx.x * 64;

    for (int idx = t; idx < DD * DD; idx += 256) sW[idx >> 6][idx & 63] = g_Wt[idx];
    for (int idx = t; idx < 64 * DD; idx += 256) {
        int r = idx >> 6, k = idx & 63;
        int n = base + r;
        float v = 0.f;
        if (n < NN) v = use_ext ? xin[n * DD + k] : g_bufB[n * DD + k];
        sA[r][k] = v;
    }
    __syncthreads();

    int jg = t & 15;        // feature group (4 feats)
    int ns = (t >> 4) * 4;  // first of 4 node rows

    float4 cv = *(const float4*)&g_c[jg * 4];
    float4 acc0 = cv, acc1 = cv, acc2 = cv, acc3 = cv;

#pragma unroll 8
    for (int k = 0; k < DD; k++) {
        float4 wv = *(const float4*)&sW[k][jg * 4];
        float a0 = sA[ns + 0][k];
        float a1 = sA[ns + 1][k];
        float a2 = sA[ns + 2][k];
        float a3 = sA[ns + 3][k];
        acc0.x += a0 * wv.x; acc0.y += a0 * wv.y; acc0.z += a0 * wv.z; acc0.w += a0 * wv.w;
        acc1.x += a1 * wv.x; acc1.y += a1 * wv.y; acc1.z += a1 * wv.z; acc1.w += a1 * wv.w;
        acc2.x += a2 * wv.x; acc2.y += a2 * wv.y; acc2.z += a2 * wv.z; acc2.w += a2 * wv.w;
        acc3.x += a3 * wv.x; acc3.y += a3 * wv.y; acc3.z += a3 * wv.z; acc3.w += a3 * wv.w;
    }

    float4 bv = *(const float4*)&bias[jg * 4];
    float4 accs[4] = {acc0, acc1, acc2, acc3};
#pragma unroll
    for (int i = 0; i < 4; i++) {
        int n = base + ns + i;
        if (n < NN) {
            *(float4*)&g_bufA[n * DD + jg * 4] = accs[i];   // lin output (no bias)
            *(float4*)&g_bufB[n * DD + jg * 4] = bv;        // seed agg with conv bias
        }
    }
}

// ---------------- scatter: agg[dst] += w * t[src], 16 threads / edge ---------
// scalar atomics (known-good path on this stack)
__global__ void __launch_bounds__(256) k_scatter(const void* __restrict__ ei,
                                                 const float* __restrict__ ew) {
    int tid = blockIdx.x * 256 + threadIdx.x;
    int e = tid >> 4;
    if (e >= NE) return;
    int jg = tid & 15;
    int is64 = g_idx64;

    int   s = ld_idx(ei, e, is64, NN);
    int   d = ld_idx(ei, (long long)NE + e, is64, NN);
    float w = ew[e];

    float4 v = *(const float4*)&g_bufA[s * DD + jg * 4];
    float* p = &g_bufB[d * DD + jg * 4];
    atomicAdd(p + 0, v.x * w);
    atomicAdd(p + 1, v.y * w);
    atomicAdd(p + 2, v.z * w);
    atomicAdd(p + 3, v.w * w);
}

// ---------------- stats: g = prelu(agg); sumsq; run-length graph segsum ------
// 8 CONTIGUOUS nodes per thread (batch sorted -> 1-2 runs), scalar flush.
__global__ void __launch_bounds__(256) k_stats(const void* __restrict__ batch,
                                               const float* __restrict__ prelu_a) {
    __shared__ double sq[16][16][4];   // [slot][jg][q0..3] = 8 KB
    int t = threadIdx.x;
    int jg = t & 15, slot = t >> 4;
    float a = prelu_a[0];
    int base = blockIdx.x * 128 + slot * 8;
    int is64 = g_idx64;

    double q0 = 0, q1 = 0, q2 = 0, q3 = 0;
    float4 acc = make_float4(0.f, 0.f, 0.f, 0.f);
    int cur = -1;

#pragma unroll
    for (int i = 0; i < 8; i++) {
        int n = base + i;
        if (n < NN) {
            int bg = ld_idx(batch, n, is64, NG);
            float4 v = *(const float4*)&g_bufB[n * DD + jg * 4];
            v.x = v.x >= 0.f ? v.x : a * v.x;
            v.y = v.y >= 0.f ? v.y : a * v.y;
            v.z = v.z >= 0.f ? v.z : a * v.z;
            v.w = v.w >= 0.f ? v.w : a * v.w;
            *(float4*)&g_bufB[n * DD + jg * 4] = v;
            q0 += (double)v.x * v.x; q1 += (double)v.y * v.y;
            q2 += (double)v.z * v.z; q3 += (double)v.w * v.w;
            if (bg != cur) {
                if (cur >= 0) {
                    float* p = &g_segsum[cur * DD + jg * 4];
                    atomicAdd(p + 0, acc.x);
                    atomicAdd(p + 1, acc.y);
                    atomicAdd(p + 2, acc.z);
                    atomicAdd(p + 3, acc.w);
                }
                cur = bg;
                acc = v;
            } else {
                acc.x += v.x; acc.y += v.y; acc.z += v.z; acc.w += v.w;
            }
        }
    }
    if (cur >= 0) {
        float* p = &g_segsum[cur * DD + jg * 4];
        atomicAdd(p + 0, acc.x);
        atomicAdd(p + 1, acc.y);
        atomicAdd(p + 2, acc.z);
        atomicAdd(p + 3, acc.w);
    }

    sq[slot][jg][0] = q0; sq[slot][jg][1] = q1;
    sq[slot][jg][2] = q2; sq[slot][jg][3] = q3;
    __syncthreads();
    for (int off = 8; off > 0; off >>= 1) {
        if (slot < off) {
#pragma unroll
            for (int m = 0; m < 4; m++) sq[slot][jg][m] += sq[slot + off][jg][m];
        }
        __syncthreads();
    }
    if (slot == 0) {
#pragma unroll
        for (int m = 0; m < 4; m++)
            atomicAdd(&g_stats[jg * 4 + m], sq[0][jg][m]);
    }
}

// ---------------- epilogue: BN params, pooled outputs, fold next W -----------
__global__ void __launch_bounds__(256) k_epi(const float* __restrict__ W,
                                             const float* __restrict__ bnw,
                                             const float* __restrict__ bnb,
                                             float* __restrict__ outp, int layer) {
    __shared__ float ss[DD], sh[DD];
    int t = threadIdx.x;
    if (t < DD) {
        // per-feature sum = column-sum of per-graph segsums
        double sum = 0.0;
#pragma unroll 4
        for (int g = 0; g < NG; g++) sum += (double)g_segsum[g * DD + t];
        double n = (double)NN;
        double mean = sum / n;
        double var = g_stats[t] / n - mean * mean;
        float istd = rsqrtf((float)var + BN_EPS);
        float s = istd * bnw[layer * DD + t];
        float shift = bnb[layer * DD + t] - (float)mean * s;
        ss[t] = s; sh[t] = shift;
        g_stats[t] = 0.0;                          // re-zero for next layer
    }
    __syncthreads();

    // pooled[g, j] = segsum[g, j] * s[j] + cnt[g] * shift[j]
    for (int idx = t; idx < NG * DD; idx += 256) {
        int g = idx >> 6, j = idx & 63;
        float val = g_segsum[idx] * ss[j] + (float)g_cnt[g] * sh[j];
        g_segsum[idx] = 0.f;                       // re-zero for next layer
        outp[g * (NL * DD) + layer * DD + j] = val;
        if (layer == NL - 1) outp[NG * NL * DD + g * DD + j] = val;  // x_stack
    }

    // fold BN into next layer's weight (transposed) and constant
    if (layer < NL - 1) {
        const float* Wn = W + (layer + 1) * DD * DD;
        for (int idx = t; idx < DD * DD; idx += 256) {
            int j = idx >> 6, k = idx & 63;
            g_Wt[k * DD + j] = ss[k] * Wn[j * DD + k];
        }
        if (t < DD) {
            float c = 0.f;
#pragma unroll
            for (int k = 0; k < DD; k++) c += sh[k] * Wn[t * DD + k];
            g_c[t] = c;
        }
    }
}

// ---------------- driver ----------------
extern "C" void kernel_launch(void* const* d_in, const int* in_sizes, int n_in,
                              void* d_out, int out_size) {
    const float* x     = (const float*)d_in[0];
    const void*  ei    = d_in[1];
    const float* ea    = (const float*)d_in[2];
    const void*  batch = d_in[3];
    const float* W     = (const float*)d_in[4];
    const float* b     = (const float*)d_in[5];
    const float* pa    = (const float*)d_in[6];
    const float* bnw   = (const float*)d_in[7];
    const float* bnb   = (const float*)d_in[8];
    float* outp = (float*)d_out;

    k_prep<<<1, 256>>>(W, ei, batch);
    for (int L = 0; L < NL; L++) {
        k_lin<<<(NN + 63) / 64, 256>>>(x, L == 0 ? 1 : 0, b + L * DD);
        k_scatter<<<(NE * 16 + 255) / 256, 256>>>(ei, ea);
        k_stats<<<(NN + 127) / 128, 256>>>(batch, pa);
        k_epi<<<1, 256>>>(W, bnw, bnb, outp, L);
    }
}

// round 11
// speedup vs baseline: 1.5290x; 1.2075x over previous
#include <cuda_runtime.h>

#define NN 100000
#define NE 1000000
#define DD 64
#define NG 128
#define NL 3
#define BN_EPS 1e-5f

// ---------------- scratch (device globals; no runtime alloc) ----------------
__device__ __align__(16) float  g_bufA[NN * DD];   // lin output t
__device__ __align__(16) float  g_bufB[NN * DD];   // node state g (next layer input)
__device__ double g_stats[DD];                     // per-feature sumsq of g
__device__ __align__(16) float  g_segsum[NG * DD]; // per-graph sums of g
__device__ int    g_cnt[NG];                       // nodes per graph
__device__ float  g_Wt[DD * DD];                   // folded, TRANSPOSED weight
__device__ float  g_c[DD];                         // folded constant
__device__ int    g_idx64;                         // 1 if int64 indices, 0 if int32
// CSR by destination node
__device__ int    g_deg[NN];                       // in-degree histogram
__device__ int    g_rowptr[NN + 1];
__device__ int    g_cursor[NN];
__device__ __align__(8) int2 g_edge[NE];           // {src, bitcast(w)} sorted by dst

__device__ __forceinline__ int clampi(int v, int lim) {
    return v < 0 ? 0 : (v >= lim ? lim - 1 : v);
}

__device__ __forceinline__ int ld_idx(const void* p, long long i, int is64, int lim) {
    int v = is64 ? (int)((const long long*)p)[i] : ((const int*)p)[i];
    return clampi(v, lim);
}

// ---------------- prologue: detect dtype, transpose W0, zero, graph counts ---
__global__ void __launch_bounds__(256) k_prep(const float* __restrict__ W,
                                              const void* __restrict__ ei,
                                              const void* __restrict__ batch) {
    int t = threadIdx.x;
    if (t == 0) {
        const int* w1 = (const int*)ei;
        const int* w2 = (const int*)batch;
        int allz = 1;
        for (int i = 1; i < 128; i += 2) allz &= (w1[i] == 0);
        for (int i = 1; i < 128; i += 2) allz &= (w2[i] == 0);
        g_idx64 = allz;
    }
    __syncthreads();
    int is64 = g_idx64;

    for (int idx = t; idx < DD * DD; idx += 256) {
        int j = idx >> 6, k = idx & 63;
        g_Wt[k * DD + j] = W[j * DD + k];          // layer 0: s = 1
    }
    for (int idx = t; idx < DD; idx += 256) { g_c[idx] = 0.f; g_stats[idx] = 0.0; }
    for (int idx = t; idx < NG * DD; idx += 256) g_segsum[idx] = 0.f;
    if (t < NG) {
        int lo = 0, hi = NN;
        while (lo < hi) {
            int m = (lo + hi) >> 1;
            int v = is64 ? (int)((const long long*)batch)[m] : ((const int*)batch)[m];
            if (v < t) lo = m + 1; else hi = m;
        }
        int a = lo;
        lo = 0; hi = NN;
        while (lo < hi) {
            int m = (lo + hi) >> 1;
            int v = is64 ? (int)((const long long*)batch)[m] : ((const int*)batch)[m];
            if (v < t + 1) lo = m + 1; else hi = m;
        }
        g_cnt[t] = lo - a;
    }
}

// ---------------- CSR build ----------------
__global__ void __launch_bounds__(256) k_zero_deg() {
    int i = blockIdx.x * 256 + threadIdx.x;
    if (i < NN) g_deg[i] = 0;
}

__global__ void __launch_bounds__(256) k_hist(const void* __restrict__ ei) {
    int e = blockIdx.x * 256 + threadIdx.x;
    if (e >= NE) return;
    int d = ld_idx(ei, (long long)NE + e, g_idx64, NN);
    atomicAdd(&g_deg[d], 1);
}

// single block, 1024 threads: exclusive scan of g_deg -> g_rowptr, g_cursor
__global__ void __launch_bounds__(1024) k_scan() {
    __shared__ int s_part[1024];
    int t = threadIdx.x;
    const int CH = (NN + 1023) / 1024;   // 98
    int lo = t * CH, hi = min(lo + CH, NN);
    int sum = 0;
    for (int i = lo; i < hi; i++) sum += g_deg[i];
    s_part[t] = sum;
    __syncthreads();
    for (int off = 1; off < 1024; off <<= 1) {
        int v = (t >= off) ? s_part[t - off] : 0;
        __syncthreads();
        s_part[t] += v;
        __syncthreads();
    }
    int run = s_part[t] - sum;           // exclusive prefix of this chunk
    for (int i = lo; i < hi; i++) {
        g_rowptr[i] = run;
        g_cursor[i] = run;
        run += g_deg[i];
    }
    if (t == 0) g_rowptr[NN] = s_part[1023];
}

__global__ void __launch_bounds__(256) k_reorder(const void* __restrict__ ei,
                                                 const float* __restrict__ ew) {
    int e = blockIdx.x * 256 + threadIdx.x;
    if (e >= NE) return;
    int is64 = g_idx64;
    int s = ld_idx(ei, e, is64, NN);
    int d = ld_idx(ei, (long long)NE + e, is64, NN);
    float w = ew[e];
    int pos = atomicAdd(&g_cursor[d], 1);
    g_edge[pos] = make_int2(s, __float_as_int(w));
}

// ---------------- lin: t = in @ Wt (+c) -> bufA ------------------------------
__global__ void __launch_bounds__(256) k_lin(const float* __restrict__ xin, int use_ext) {
    __shared__ __align__(16) float sA[64][64];
    __shared__ __align__(16) float sW[64][64];   // sW[k][j]
    int t = threadIdx.x;
    int base = blockIdx.x * 64;

    for (int idx = t; idx < DD * DD; idx += 256) sW[idx >> 6][idx & 63] = g_Wt[idx];
    for (int idx = t; idx < 64 * DD; idx += 256) {
        int r = idx >> 6, k = idx & 63;
        int n = base + r;
        float v = 0.f;
        if (n < NN) v = use_ext ? xin[n * DD + k] : g_bufB[n * DD + k];
        sA[r][k] = v;
    }
    __syncthreads();

    int jg = t & 15;        // feature group (4 feats)
    int ns = (t >> 4) * 4;  // first of 4 node rows

    float4 cv = *(const float4*)&g_c[jg * 4];
    float4 acc0 = cv, acc1 = cv, acc2 = cv, acc3 = cv;

#pragma unroll 8
    for (int k = 0; k < DD; k++) {
        float4 wv = *(const float4*)&sW[k][jg * 4];
        float a0 = sA[ns + 0][k];
        float a1 = sA[ns + 1][k];
        float a2 = sA[ns + 2][k];
        float a3 = sA[ns + 3][k];
        acc0.x += a0 * wv.x; acc0.y += a0 * wv.y; acc0.z += a0 * wv.z; acc0.w += a0 * wv.w;
        acc1.x += a1 * wv.x; acc1.y += a1 * wv.y; acc1.z += a1 * wv.z; acc1.w += a1 * wv.w;
        acc2.x += a2 * wv.x; acc2.y += a2 * wv.y; acc2.z += a2 * wv.z; acc2.w += a2 * wv.w;
        acc3.x += a3 * wv.x; acc3.y += a3 * wv.y; acc3.z += a3 * wv.z; acc3.w += a3 * wv.w;
    }

    float4 accs[4] = {acc0, acc1, acc2, acc3};
#pragma unroll
    for (int i = 0; i < 4; i++) {
        int n = base + ns + i;
        if (n < NN) *(float4*)&g_bufA[n * DD + jg * 4] = accs[i];
    }
}

// ---------------- gather: agg + bias -> prelu -> g; fused sumsq + segsum -----
// 16 threads/node; group of 16 threads handles 8 CONTIGUOUS nodes (run-length).
__global__ void __launch_bounds__(256) k_gather(const void* __restrict__ batch,
                                                const float* __restrict__ prelu_a,
                                                const float* __restrict__ bias) {
    __shared__ double sq[16][16][4];   // [slot][jg][q0..3] = 8 KB
    int t = threadIdx.x;
    int jg = t & 15, slot = t >> 4;
    float a = prelu_a[0];
    int base = blockIdx.x * 128 + slot * 8;
    int is64 = g_idx64;
    float4 bv = *(const float4*)&bias[jg * 4];

    double q0 = 0, q1 = 0, q2 = 0, q3 = 0;
    float4 segacc = make_float4(0.f, 0.f, 0.f, 0.f);
    int cur = -1;

#pragma unroll 1
    for (int i = 0; i < 8; i++) {
        int n = base + i;
        if (n < NN) {
            int st = g_rowptr[n], en = g_rowptr[n + 1];   // broadcast
            float4 v = bv;
            for (int e = st; e < en; e++) {
                int2 ed = g_edge[e];                      // broadcast 8B
                float w = __int_as_float(ed.y);
                float4 x = *(const float4*)&g_bufA[ed.x * DD + jg * 4];
                v.x += w * x.x; v.y += w * x.y; v.z += w * x.z; v.w += w * x.w;
            }
            v.x = v.x >= 0.f ? v.x : a * v.x;
            v.y = v.y >= 0.f ? v.y : a * v.y;
            v.z = v.z >= 0.f ? v.z : a * v.z;
            v.w = v.w >= 0.f ? v.w : a * v.w;
            *(float4*)&g_bufB[n * DD + jg * 4] = v;
            q0 += (double)v.x * v.x; q1 += (double)v.y * v.y;
            q2 += (double)v.z * v.z; q3 += (double)v.w * v.w;
            int bg = ld_idx(batch, n, is64, NG);
            if (bg != cur) {
                if (cur >= 0) {
                    float* p = &g_segsum[cur * DD + jg * 4];
                    atomicAdd(p + 0, segacc.x);
                    atomicAdd(p + 1, segacc.y);
                    atomicAdd(p + 2, segacc.z);
                    atomicAdd(p + 3, segacc.w);
                }
                cur = bg;
                segacc = v;
            } else {
                segacc.x += v.x; segacc.y += v.y; segacc.z += v.z; segacc.w += v.w;
            }
        }
    }
    if (cur >= 0) {
        float* p = &g_segsum[cur * DD + jg * 4];
        atomicAdd(p + 0, segacc.x);
        atomicAdd(p + 1, segacc.y);
        atomicAdd(p + 2, segacc.z);
        atomicAdd(p + 3, segacc.w);
    }

    sq[slot][jg][0] = q0; sq[slot][jg][1] = q1;
    sq[slot][jg][2] = q2; sq[slot][jg][3] = q3;
    __syncthreads();
    for (int off = 8; off > 0; off >>= 1) {
        if (slot < off) {
#pragma unroll
            for (int m = 0; m < 4; m++) sq[slot][jg][m] += sq[slot + off][jg][m];
        }
        __syncthreads();
    }
    if (slot == 0) {
#pragma unroll
        for (int m = 0; m < 4; m++)
            atomicAdd(&g_stats[jg * 4 + m], sq[0][jg][m]);
    }
}

// ---------------- epilogue: BN params, pooled outputs, fold next W -----------
__global__ void __launch_bounds__(256) k_epi(const float* __restrict__ W,
                                             const float* __restrict__ bnw,
                                             const float* __restrict__ bnb,
                                             float* __restrict__ outp, int layer) {
    __shared__ float ss[DD], sh[DD];
    int t = threadIdx.x;
    if (t < DD) {
        double sum = 0.0;
#pragma unroll 4
        for (int g = 0; g < NG; g++) sum += (double)g_segsum[g * DD + t];
        double n = (double)NN;
        double mean = sum / n;
        double var = g_stats[t] / n - mean * mean;
        float istd = rsqrtf((float)var + BN_EPS);
        float s = istd * bnw[layer * DD + t];
        float shift = bnb[layer * DD + t] - (float)mean * s;
        ss[t] = s; sh[t] = shift;
        g_stats[t] = 0.0;
    }
    __syncthreads();

    for (int idx = t; idx < NG * DD; idx += 256) {
        int g = idx >> 6, j = idx & 63;
        float val = g_segsum[idx] * ss[j] + (float)g_cnt[g] * sh[j];
        g_segsum[idx] = 0.f;
        outp[g * (NL * DD) + layer * DD + j] = val;
        if (layer == NL - 1) outp[NG * NL * DD + g * DD + j] = val;
    }

    if (layer < NL - 1) {
        const float* Wn = W + (layer + 1) * DD * DD;
        for (int idx = t; idx < DD * DD; idx += 256) {
            int j = idx >> 6, k = idx & 63;
            g_Wt[k * DD + j] = ss[k] * Wn[j * DD + k];
        }
        if (t < DD) {
            float c = 0.f;
#pragma unroll
            for (int k = 0; k < DD; k++) c += sh[k] * Wn[t * DD + k];
            g_c[t] = c;
        }
    }
}

// ---------------- driver ----------------
extern "C" void kernel_launch(void* const* d_in, const int* in_sizes, int n_in,
                              void* d_out, int out_size) {
    const float* x     = (const float*)d_in[0];
    const void*  ei    = d_in[1];
    const float* ea    = (const float*)d_in[2];
    const void*  batch = d_in[3];
    const float* W     = (const float*)d_in[4];
    const float* b     = (const float*)d_in[5];
    const float* pa    = (const float*)d_in[6];
    const float* bnw   = (const float*)d_in[7];
    const float* bnb   = (const float*)d_in[8];
    float* outp = (float*)d_out;

    k_prep<<<1, 256>>>(W, ei, batch);
    k_zero_deg<<<(NN + 255) / 256, 256>>>();
    k_hist<<<(NE + 255) / 256, 256>>>(ei);
    k_scan<<<1, 1024>>>();
    k_reorder<<<(NE + 255) / 256, 256>>>(ei, ea);
    for (int L = 0; L < NL; L++) {
        k_lin<<<(NN + 63) / 64, 256>>>(x, L == 0 ? 1 : 0);
        k_gather<<<(NN + 127) / 128, 256>>>(batch, pa, b + L * DD);
        k_epi<<<1, 256>>>(W, bnw, bnb, outp, L);
    }
}

// round 12
// speedup vs baseline: 2.1353x; 1.3965x over previous
#include <cuda_runtime.h>

#define NN 100000
#define NE 1000000
#define DD 64
#define NG 128
#define NL 3
#define BN_EPS 1e-5f
#define SCAN_B 98           // ceil(NN/1024)

// ---------------- scratch (device globals; no runtime alloc) ----------------
__device__ __align__(16) float  g_bufA[NN * DD];   // lin output t
__device__ __align__(16) float  g_bufB[NN * DD];   // node state g (next layer input)
__device__ double g_stats[DD];                     // per-feature sumsq of g
__device__ __align__(16) float  g_segsum[NG * DD]; // per-graph sums of g
__device__ int    g_cnt[NG];                       // nodes per graph
__device__ float  g_Wt[DD * DD];                   // folded, TRANSPOSED weight
__device__ float  g_c[DD];                         // folded constant
__device__ int    g_idx64;                         // 1 if int64 indices, 0 if int32
// CSR by destination node
__device__ int    g_deg[NN];                       // in-degree histogram
__device__ int    g_rowptr[NN + 1];
__device__ int    g_cursor[NN];
__device__ int    g_part[128];                     // per-block partial sums (SCAN_B used)
__device__ __align__(8) int2 g_edge[NE];           // {src, bitcast(w)} sorted by dst

__device__ __forceinline__ int clampi(int v, int lim) {
    return v < 0 ? 0 : (v >= lim ? lim - 1 : v);
}

__device__ __forceinline__ int ld_idx(const void* p, long long i, int is64, int lim) {
    int v = is64 ? (int)((const long long*)p)[i] : ((const int*)p)[i];
    return clampi(v, lim);
}

// ---------------- prologue: detect dtype, transpose W0, zero, graph counts ---
__global__ void __launch_bounds__(256) k_prep(const float* __restrict__ W,
                                              const void* __restrict__ ei,
                                              const void* __restrict__ batch) {
    int t = threadIdx.x;
    if (t == 0) {
        const int* w1 = (const int*)ei;
        const int* w2 = (const int*)batch;
        int allz = 1;
        for (int i = 1; i < 128; i += 2) allz &= (w1[i] == 0);
        for (int i = 1; i < 128; i += 2) allz &= (w2[i] == 0);
        g_idx64 = allz;
    }
    __syncthreads();
    int is64 = g_idx64;

    for (int idx = t; idx < DD * DD; idx += 256) {
        int j = idx >> 6, k = idx & 63;
        g_Wt[k * DD + j] = W[j * DD + k];          // layer 0: s = 1
    }
    for (int idx = t; idx < DD; idx += 256) { g_c[idx] = 0.f; g_stats[idx] = 0.0; }
    for (int idx = t; idx < NG * DD; idx += 256) g_segsum[idx] = 0.f;
    if (t < NG) {
        int lo = 0, hi = NN;
        while (lo < hi) {
            int m = (lo + hi) >> 1;
            int v = is64 ? (int)((const long long*)batch)[m] : ((const int*)batch)[m];
            if (v < t) lo = m + 1; else hi = m;
        }
        int a = lo;
        lo = 0; hi = NN;
        while (lo < hi) {
            int m = (lo + hi) >> 1;
            int v = is64 ? (int)((const long long*)batch)[m] : ((const int*)batch)[m];
            if (v < t + 1) lo = m + 1; else hi = m;
        }
        g_cnt[t] = lo - a;
    }
}

// ---------------- CSR build ----------------
__global__ void __launch_bounds__(256) k_zero_deg() {
    int i = blockIdx.x * 256 + threadIdx.x;
    if (i < NN) g_deg[i] = 0;
}

__global__ void __launch_bounds__(256) k_hist(const void* __restrict__ ei) {
    int e = blockIdx.x * 256 + threadIdx.x;
    if (e >= NE) return;
    int d = ld_idx(ei, (long long)NE + e, g_idx64, NN);
    atomicAdd(&g_deg[d], 1);
}

// phase 1: per-block sums of g_deg  (grid SCAN_B, block 1024)
__global__ void __launch_bounds__(1024) k_scan1() {
    __shared__ int swarp[32];
    int t = threadIdx.x;
    int i = blockIdx.x * 1024 + t;
    int v = (i < NN) ? g_deg[i] : 0;
    int lane = t & 31, wid = t >> 5;
    int s = v;
#pragma unroll
    for (int off = 16; off > 0; off >>= 1) s += __shfl_down_sync(0xffffffffu, s, off);
    if (lane == 0) swarp[wid] = s;
    __syncthreads();
    if (wid == 0) {
        s = swarp[lane];
#pragma unroll
        for (int off = 16; off > 0; off >>= 1) s += __shfl_down_sync(0xffffffffu, s, off);
        if (lane == 0) g_part[blockIdx.x] = s;
    }
}

// phase 2: exclusive scan of SCAN_B partials (1 block, 128 threads, smem)
__global__ void __launch_bounds__(128) k_scan2() {
    __shared__ int sp[128];
    int t = threadIdx.x;
    int v = (t < SCAN_B) ? g_part[t] : 0;
    sp[t] = v;
    __syncthreads();
    for (int off = 1; off < 128; off <<= 1) {
        int u = (t >= off) ? sp[t - off] : 0;
        __syncthreads();
        sp[t] += u;
        __syncthreads();
    }
    if (t < SCAN_B) g_part[t] = sp[t] - v;         // exclusive
    if (t == 127) g_rowptr[NN] = sp[127];          // total
}

// phase 3: in-block exclusive scan + block offset -> rowptr, cursor
__global__ void __launch_bounds__(1024) k_scan3() {
    __shared__ int swarp[32];
    int t = threadIdx.x;
    int i = blockIdx.x * 1024 + t;
    int v = (i < NN) ? g_deg[i] : 0;
    int lane = t & 31, wid = t >> 5;
    // warp inclusive scan
    int inc = v;
#pragma unroll
    for (int off = 1; off < 32; off <<= 1) {
        int u = __shfl_up_sync(0xffffffffu, inc, off);
        if (lane >= off) inc += u;
    }
    if (lane == 31) swarp[wid] = inc;
    __syncthreads();
    if (wid == 0) {
        int ws = swarp[lane];
#pragma unroll
        for (int off = 1; off < 32; off <<= 1) {
            int u = __shfl_up_sync(0xffffffffu, ws, off);
            if (lane >= off) ws += u;
        }
        swarp[lane] = ws;
    }
    __syncthreads();
    int warpoff = (wid == 0) ? 0 : swarp[wid - 1];
    int excl = g_part[blockIdx.x] + warpoff + inc - v;
    if (i < NN) {
        g_rowptr[i] = excl;
        g_cursor[i] = excl;
    }
}

__global__ void __launch_bounds__(256) k_reorder(const void* __restrict__ ei,
                                                 const float* __restrict__ ew) {
    int e = blockIdx.x * 256 + threadIdx.x;
    if (e >= NE) return;
    int is64 = g_idx64;
    int s = ld_idx(ei, e, is64, NN);
    int d = ld_idx(ei, (long long)NE + e, is64, NN);
    float w = ew[e];
    int pos = atomicAdd(&g_cursor[d], 1);
    g_edge[pos] = make_int2(s, __float_as_int(w));
}

// ---------------- lin: t = in @ Wt (+c) -> bufA ------------------------------
__global__ void __launch_bounds__(256) k_lin(const float* __restrict__ xin, int use_ext) {
    __shared__ __align__(16) float sA[64][64];
    __shared__ __align__(16) float sW[64][64];   // sW[k][j]
    int t = threadIdx.x;
    int base = blockIdx.x * 64;

    for (int idx = t; idx < DD * DD; idx += 256) sW[idx >> 6][idx & 63] = g_Wt[idx];
    for (int idx = t; idx < 64 * DD; idx += 256) {
        int r = idx >> 6, k = idx & 63;
        int n = base + r;
        float v = 0.f;
        if (n < NN) v = use_ext ? xin[n * DD + k] : g_bufB[n * DD + k];
        sA[r][k] = v;
    }
    __syncthreads();

    int jg = t & 15;        // feature group (4 feats)
    int ns = (t >> 4) * 4;  // first of 4 node rows

    float4 cv = *(const float4*)&g_c[jg * 4];
    float4 acc0 = cv, acc1 = cv, acc2 = cv, acc3 = cv;

#pragma unroll 8
    for (int k = 0; k < DD; k++) {
        float4 wv = *(const float4*)&sW[k][jg * 4];
        float a0 = sA[ns + 0][k];
        float a1 = sA[ns + 1][k];
        float a2 = sA[ns + 2][k];
        float a3 = sA[ns + 3][k];
        acc0.x += a0 * wv.x; acc0.y += a0 * wv.y; acc0.z += a0 * wv.z; acc0.w += a0 * wv.w;
        acc1.x += a1 * wv.x; acc1.y += a1 * wv.y; acc1.z += a1 * wv.z; acc1.w += a1 * wv.w;
        acc2.x += a2 * wv.x; acc2.y += a2 * wv.y; acc2.z += a2 * wv.z; acc2.w += a2 * wv.w;
        acc3.x += a3 * wv.x; acc3.y += a3 * wv.y; acc3.z += a3 * wv.z; acc3.w += a3 * wv.w;
    }

    float4 accs[4] = {acc0, acc1, acc2, acc3};
#pragma unroll
    for (int i = 0; i < 4; i++) {
        int n = base + ns + i;
        if (n < NN) *(float4*)&g_bufA[n * DD + jg * 4] = accs[i];
    }
}

// ---------------- gather: agg + bias -> prelu -> g; fused sumsq + segsum -----
// 16 threads/node; group of 16 threads handles 8 CONTIGUOUS nodes (run-length).
__global__ void __launch_bounds__(256) k_gather(const void* __restrict__ batch,
                                                const float* __restrict__ prelu_a,
                                                const float* __restrict__ bias) {
    __shared__ double sq[16][16][4];   // [slot][jg][q0..3] = 8 KB
    int t = threadIdx.x;
    int jg = t & 15, slot = t >> 4;
    float a = prelu_a[0];
    int base = blockIdx.x * 128 + slot * 8;
    int is64 = g_idx64;
    float4 bv = *(const float4*)&bias[jg * 4];

    double q0 = 0, q1 = 0, q2 = 0, q3 = 0;
    float4 segacc = make_float4(0.f, 0.f, 0.f, 0.f);
    int cur = -1;

#pragma unroll 1
    for (int i = 0; i < 8; i++) {
        int n = base + i;
        if (n < NN) {
            int st = g_rowptr[n], en = g_rowptr[n + 1];   // broadcast
            float4 v = bv;
            for (int e = st; e < en; e++) {
                int2 ed = g_edge[e];                      // broadcast 8B
                float w = __int_as_float(ed.y);
                float4 x = *(const float4*)&g_bufA[ed.x * DD + jg * 4];
                v.x += w * x.x; v.y += w * x.y; v.z += w * x.z; v.w += w * x.w;
            }
            v.x = v.x >= 0.f ? v.x : a * v.x;
            v.y = v.y >= 0.f ? v.y : a * v.y;
            v.z = v.z >= 0.f ? v.z : a * v.z;
            v.w = v.w >= 0.f ? v.w : a * v.w;
            *(float4*)&g_bufB[n * DD + jg * 4] = v;
            q0 += (double)v.x * v.x; q1 += (double)v.y * v.y;
            q2 += (double)v.z * v.z; q3 += (double)v.w * v.w;
            int bg = ld_idx(batch, n, is64, NG);
            if (bg != cur) {
                if (cur >= 0) {
                    float* p = &g_segsum[cur * DD + jg * 4];
                    atomicAdd(p + 0, segacc.x);
                    atomicAdd(p + 1, segacc.y);
                    atomicAdd(p + 2, segacc.z);
                    atomicAdd(p + 3, segacc.w);
                }
                cur = bg;
                segacc = v;
            } else {
                segacc.x += v.x; segacc.y += v.y; segacc.z += v.z; segacc.w += v.w;
            }
        }
    }
    if (cur >= 0) {
        float* p = &g_segsum[cur * DD + jg * 4];
        atomicAdd(p + 0, segacc.x);
        atomicAdd(p + 1, segacc.y);
        atomicAdd(p + 2, segacc.z);
        atomicAdd(p + 3, segacc.w);
    }

    sq[slot][jg][0] = q0; sq[slot][jg][1] = q1;
    sq[slot][jg][2] = q2; sq[slot][jg][3] = q3;
    __syncthreads();
    for (int off = 8; off > 0; off >>= 1) {
        if (slot < off) {
#pragma unroll
            for (int m = 0; m < 4; m++) sq[slot][jg][m] += sq[slot + off][jg][m];
        }
        __syncthreads();
    }
    if (slot == 0) {
#pragma unroll
        for (int m = 0; m < 4; m++)
            atomicAdd(&g_stats[jg * 4 + m], sq[0][jg][m]);
    }
}

// ---------------- epilogue: BN params, pooled outputs, fold next W -----------
__global__ void __launch_bounds__(256) k_epi(const float* __restrict__ W,
                                             const float* __restrict__ bnw,
                                             const float* __restrict__ bnb,
                                             float* __restrict__ outp, int layer) {
    __shared__ float ss[DD], sh[DD];
    int t = threadIdx.x;
    if (t < DD) {
        double sum = 0.0;
#pragma unroll 4
        for (int g = 0; g < NG; g++) sum += (double)g_segsum[g * DD + t];
        double n = (double)NN;
        double mean = sum / n;
        double var = g_stats[t] / n - mean * mean;
        float istd = rsqrtf((float)var + BN_EPS);
        float s = istd * bnw[layer * DD + t];
        float shift = bnb[layer * DD + t] - (float)mean * s;
        ss[t] = s; sh[t] = shift;
        g_stats[t] = 0.0;
    }
    __syncthreads();

    for (int idx = t; idx < NG * DD; idx += 256) {
        int g = idx >> 6, j = idx & 63;
        float val = g_segsum[idx] * ss[j] + (float)g_cnt[g] * sh[j];
        g_segsum[idx] = 0.f;
        outp[g * (NL * DD) + layer * DD + j] = val;
        if (layer == NL - 1) outp[NG * NL * DD + g * DD + j] = val;
    }

    if (layer < NL - 1) {
        const float* Wn = W + (layer + 1) * DD * DD;
        for (int idx = t; idx < DD * DD; idx += 256) {
            int j = idx >> 6, k = idx & 63;
            g_Wt[k * DD + j] = ss[k] * Wn[j * DD + k];
        }
        if (t < DD) {
            float c = 0.f;
#pragma unroll
            for (int k = 0; k < DD; k++) c += sh[k] * Wn[t * DD + k];
            g_c[t] = c;
        }
    }
}

// ---------------- driver ----------------
extern "C" void kernel_launch(void* const* d_in, const int* in_sizes, int n_in,
                              void* d_out, int out_size) {
    const float* x     = (const float*)d_in[0];
    const void*  ei    = d_in[1];
    const float* ea    = (const float*)d_in[2];
    const void*  batch = d_in[3];
    const float* W     = (const float*)d_in[4];
    const float* b     = (const float*)d_in[5];
    const float* pa    = (const float*)d_in[6];
    const float* bnw   = (const float*)d_in[7];
    const float* bnb   = (const float*)d_in[8];
    float* outp = (float*)d_out;

    k_prep<<<1, 256>>>(W, ei, batch);
    k_zero_deg<<<(NN + 255) / 256, 256>>>();
    k_hist<<<(NE + 255) / 256, 256>>>(ei);
    k_scan1<<<SCAN_B, 1024>>>();
    k_scan2<<<1, 128>>>();
    k_scan3<<<SCAN_B, 1024>>>();
    k_reorder<<<(NE + 255) / 256, 256>>>(ei, ea);
    for (int L = 0; L < NL; L++) {
        k_lin<<<(NN + 63) / 64, 256>>>(x, L == 0 ? 1 : 0);
        k_gather<<<(NN + 127) / 128, 256>>>(batch, pa, b + L * DD);
        k_epi<<<1, 256>>>(W, bnw, bnb, outp, L);
    }
}

// round 13
// speedup vs baseline: 2.3636x; 1.1070x over previous
#include <cuda_runtime.h>

#define NN 100000
#define NE 1000000
#define DD 64
#define NG 128
#define NL 3
#define BN_EPS 1e-5f
#define SCAN_B 98           // ceil(NN/1024)

// ---------------- scratch (device globals; no runtime alloc) ----------------
__device__ __align__(16) float  g_bufA[NN * DD];   // lin output t
__device__ __align__(16) float  g_bufB[NN * DD];   // node state g (next layer input)
__device__ double g_stats[DD];                     // per-feature sumsq of g
__device__ __align__(16) float  g_segsum[NG * DD]; // per-graph sums of g
__device__ int    g_cnt[NG];                       // nodes per graph
__device__ float  g_Wt[DD * DD];                   // folded, TRANSPOSED weight
__device__ float  g_c[DD];                         // folded constant
__device__ int    g_idx64;                         // 1 if int64 indices, 0 if int32
// CSR by destination node
__device__ int    g_deg[NN];                       // in-degree histogram
__device__ int    g_rowptr[NN + 1];
__device__ int    g_cursor[NN];
__device__ int    g_part[128];                     // per-block partial sums (SCAN_B used)
__device__ __align__(8) int2 g_edge[NE];           // {src, bitcast(w)} sorted by dst

__device__ __forceinline__ int clampi(int v, int lim) {
    return v < 0 ? 0 : (v >= lim ? lim - 1 : v);
}

__device__ __forceinline__ int ld_idx(const void* p, long long i, int is64, int lim) {
    int v = is64 ? (int)((const long long*)p)[i] : ((const int*)p)[i];
    return clampi(v, lim);
}

// ---------------- prologue: detect dtype, transpose W0, zero, graph counts ---
__global__ void __launch_bounds__(256) k_prep(const float* __restrict__ W,
                                              const void* __restrict__ ei,
                                              const void* __restrict__ batch) {
    int t = threadIdx.x;
    if (t == 0) {
        const int* w1 = (const int*)ei;
        const int* w2 = (const int*)batch;
        int allz = 1;
        for (int i = 1; i < 128; i += 2) allz &= (w1[i] == 0);
        for (int i = 1; i < 128; i += 2) allz &= (w2[i] == 0);
        g_idx64 = allz;
    }
    __syncthreads();
    int is64 = g_idx64;

    for (int idx = t; idx < DD * DD; idx += 256) {
        int j = idx >> 6, k = idx & 63;
        g_Wt[k * DD + j] = W[j * DD + k];          // layer 0: s = 1
    }
    for (int idx = t; idx < DD; idx += 256) { g_c[idx] = 0.f; g_stats[idx] = 0.0; }
    for (int idx = t; idx < NG * DD; idx += 256) g_segsum[idx] = 0.f;
    if (t < NG) {
        int lo = 0, hi = NN;
        while (lo < hi) {
            int m = (lo + hi) >> 1;
            int v = is64 ? (int)((const long long*)batch)[m] : ((const int*)batch)[m];
            if (v < t) lo = m + 1; else hi = m;
        }
        int a = lo;
        lo = 0; hi = NN;
        while (lo < hi) {
            int m = (lo + hi) >> 1;
            int v = is64 ? (int)((const long long*)batch)[m] : ((const int*)batch)[m];
            if (v < t + 1) lo = m + 1; else hi = m;
        }
        g_cnt[t] = lo - a;
    }
}

// ---------------- CSR build ----------------
__global__ void __launch_bounds__(256) k_zero_deg() {
    int i = blockIdx.x * 256 + threadIdx.x;
    if (i < NN) g_deg[i] = 0;
}

__global__ void __launch_bounds__(256) k_hist(const void* __restrict__ ei) {
    int e = blockIdx.x * 256 + threadIdx.x;
    if (e >= NE) return;
    int d = ld_idx(ei, (long long)NE + e, g_idx64, NN);
    atomicAdd(&g_deg[d], 1);
}

// phase 1: per-block sums of g_deg  (grid SCAN_B, block 1024)
__global__ void __launch_bounds__(1024) k_scan1() {
    __shared__ int swarp[32];
    int t = threadIdx.x;
    int i = blockIdx.x * 1024 + t;
    int v = (i < NN) ? g_deg[i] : 0;
    int lane = t & 31, wid = t >> 5;
    int s = v;
#pragma unroll
    for (int off = 16; off > 0; off >>= 1) s += __shfl_down_sync(0xffffffffu, s, off);
    if (lane == 0) swarp[wid] = s;
    __syncthreads();
    if (wid == 0) {
        s = swarp[lane];
#pragma unroll
        for (int off = 16; off > 0; off >>= 1) s += __shfl_down_sync(0xffffffffu, s, off);
        if (lane == 0) g_part[blockIdx.x] = s;
    }
}

// phase 2: exclusive scan of SCAN_B partials (1 block, 128 threads, smem)
__global__ void __launch_bounds__(128) k_scan2() {
    __shared__ int sp[128];
    int t = threadIdx.x;
    int v = (t < SCAN_B) ? g_part[t] : 0;
    sp[t] = v;
    __syncthreads();
    for (int off = 1; off < 128; off <<= 1) {
        int u = (t >= off) ? sp[t - off] : 0;
        __syncthreads();
        sp[t] += u;
        __syncthreads();
    }
    if (t < SCAN_B) g_part[t] = sp[t] - v;         // exclusive
    if (t == 127) g_rowptr[NN] = sp[127];          // total
}

// phase 3: in-block exclusive scan + block offset -> rowptr, cursor
__global__ void __launch_bounds__(1024) k_scan3() {
    __shared__ int swarp[32];
    int t = threadIdx.x;
    int i = blockIdx.x * 1024 + t;
    int v = (i < NN) ? g_deg[i] : 0;
    int lane = t & 31, wid = t >> 5;
    int inc = v;
#pragma unroll
    for (int off = 1; off < 32; off <<= 1) {
        int u = __shfl_up_sync(0xffffffffu, inc, off);
        if (lane >= off) inc += u;
    }
    if (lane == 31) swarp[wid] = inc;
    __syncthreads();
    if (wid == 0) {
        int ws = swarp[lane];
#pragma unroll
        for (int off = 1; off < 32; off <<= 1) {
            int u = __shfl_up_sync(0xffffffffu, ws, off);
            if (lane >= off) ws += u;
        }
        swarp[lane] = ws;
    }
    __syncthreads();
    int warpoff = (wid == 0) ? 0 : swarp[wid - 1];
    int excl = g_part[blockIdx.x] + warpoff + inc - v;
    if (i < NN) {
        g_rowptr[i] = excl;
        g_cursor[i] = excl;
    }
}

__global__ void __launch_bounds__(256) k_reorder(const void* __restrict__ ei,
                                                 const float* __restrict__ ew) {
    int e = blockIdx.x * 256 + threadIdx.x;
    if (e >= NE) return;
    int is64 = g_idx64;
    int s = ld_idx(ei, e, is64, NN);
    int d = ld_idx(ei, (long long)NE + e, is64, NN);
    float w = ew[e];
    int pos = atomicAdd(&g_cursor[d], 1);
    g_edge[pos] = make_int2(s, __float_as_int(w));
}

// ---------------- lin: t = in @ Wt (+c) -> bufA ------------------------------
__global__ void __launch_bounds__(256) k_lin(const float* __restrict__ xin, int use_ext) {
    __shared__ __align__(16) float sA[64][64];
    __shared__ __align__(16) float sW[64][64];   // sW[k][j]
    int t = threadIdx.x;
    int base = blockIdx.x * 64;

    for (int idx = t; idx < DD * DD; idx += 256) sW[idx >> 6][idx & 63] = g_Wt[idx];
    for (int idx = t; idx < 64 * DD; idx += 256) {
        int r = idx >> 6, k = idx & 63;
        int n = base + r;
        float v = 0.f;
        if (n < NN) v = use_ext ? xin[n * DD + k] : g_bufB[n * DD + k];
        sA[r][k] = v;
    }
    __syncthreads();

    int jg = t & 15;        // feature group (4 feats)
    int ns = (t >> 4) * 4;  // first of 4 node rows

    float4 cv = *(const float4*)&g_c[jg * 4];
    float4 acc0 = cv, acc1 = cv, acc2 = cv, acc3 = cv;

#pragma unroll 8
    for (int k = 0; k < DD; k++) {
        float4 wv = *(const float4*)&sW[k][jg * 4];
        float a0 = sA[ns + 0][k];
        float a1 = sA[ns + 1][k];
        float a2 = sA[ns + 2][k];
        float a3 = sA[ns + 3][k];
        acc0.x += a0 * wv.x; acc0.y += a0 * wv.y; acc0.z += a0 * wv.z; acc0.w += a0 * wv.w;
        acc1.x += a1 * wv.x; acc1.y += a1 * wv.y; acc1.z += a1 * wv.z; acc1.w += a1 * wv.w;
        acc2.x += a2 * wv.x; acc2.y += a2 * wv.y; acc2.z += a2 * wv.z; acc2.w += a2 * wv.w;
        acc3.x += a3 * wv.x; acc3.y += a3 * wv.y; acc3.z += a3 * wv.z; acc3.w += a3 * wv.w;
    }

    float4 accs[4] = {acc0, acc1, acc2, acc3};
#pragma unroll
    for (int i = 0; i < 4; i++) {
        int n = base + ns + i;
        if (n < NN) *(float4*)&g_bufA[n * DD + jg * 4] = accs[i];
    }
}

// ---------------- gather: agg + bias -> prelu -> g; fused sumsq + segsum -----
// 16 threads/node; group of 16 threads handles 8 CONTIGUOUS nodes (run-length).
// Edge loop unrolled x4 with independent accumulators for MLP.
__global__ void __launch_bounds__(256) k_gather(const void* __restrict__ batch,
                                                const float* __restrict__ prelu_a,
                                                const float* __restrict__ bias) {
    __shared__ double sq[16][16][4];   // [slot][jg][q0..3] = 8 KB
    int t = threadIdx.x;
    int jg = t & 15, slot = t >> 4;
    float a = prelu_a[0];
    int base = blockIdx.x * 128 + slot * 8;
    int is64 = g_idx64;
    float4 bv = *(const float4*)&bias[jg * 4];

    double q0 = 0, q1 = 0, q2 = 0, q3 = 0;
    float4 segacc = make_float4(0.f, 0.f, 0.f, 0.f);
    int cur = -1;

#pragma unroll 1
    for (int i = 0; i < 8; i++) {
        int n = base + i;
        if (n < NN) {
            int st = g_rowptr[n], en = g_rowptr[n + 1];   // broadcast
            float4 v = bv;
            float4 va1 = make_float4(0.f, 0.f, 0.f, 0.f);
            float4 va2 = make_float4(0.f, 0.f, 0.f, 0.f);
            float4 va3 = make_float4(0.f, 0.f, 0.f, 0.f);
            int e = st;
            for (; e + 4 <= en; e += 4) {
                int2 e0 = g_edge[e + 0];
                int2 e1 = g_edge[e + 1];
                int2 e2 = g_edge[e + 2];
                int2 e3 = g_edge[e + 3];
                float4 x0 = *(const float4*)&g_bufA[e0.x * DD + jg * 4];
                float4 x1 = *(const float4*)&g_bufA[e1.x * DD + jg * 4];
                float4 x2 = *(const float4*)&g_bufA[e2.x * DD + jg * 4];
                float4 x3 = *(const float4*)&g_bufA[e3.x * DD + jg * 4];
                float w0 = __int_as_float(e0.y);
                float w1 = __int_as_float(e1.y);
                float w2 = __int_as_float(e2.y);
                float w3 = __int_as_float(e3.y);
                v.x   += w0 * x0.x; v.y   += w0 * x0.y; v.z   += w0 * x0.z; v.w   += w0 * x0.w;
                va1.x += w1 * x1.x; va1.y += w1 * x1.y; va1.z += w1 * x1.z; va1.w += w1 * x1.w;
                va2.x += w2 * x2.x; va2.y += w2 * x2.y; va2.z += w2 * x2.z; va2.w += w2 * x2.w;
                va3.x += w3 * x3.x; va3.y += w3 * x3.y; va3.z += w3 * x3.z; va3.w += w3 * x3.w;
            }
            for (; e < en; e++) {
                int2 ed = g_edge[e];
                float w = __int_as_float(ed.y);
                float4 x = *(const float4*)&g_bufA[ed.x * DD + jg * 4];
                v.x += w * x.x; v.y += w * x.y; v.z += w * x.z; v.w += w * x.w;
            }
            v.x += va1.x + va2.x + va3.x;
            v.y += va1.y + va2.y + va3.y;
            v.z += va1.z + va2.z + va3.z;
            v.w += va1.w + va2.w + va3.w;

            v.x = v.x >= 0.f ? v.x : a * v.x;
            v.y = v.y >= 0.f ? v.y : a * v.y;
            v.z = v.z >= 0.f ? v.z : a * v.z;
            v.w = v.w >= 0.f ? v.w : a * v.w;
            *(float4*)&g_bufB[n * DD + jg * 4] = v;
            q0 += (double)v.x * v.x; q1 += (double)v.y * v.y;
            q2 += (double)v.z * v.z; q3 += (double)v.w * v.w;
            int bg = ld_idx(batch, n, is64, NG);
            if (bg != cur) {
                if (cur >= 0) {
                    float* p = &g_segsum[cur * DD + jg * 4];
                    atomicAdd(p + 0, segacc.x);
                    atomicAdd(p + 1, segacc.y);
                    atomicAdd(p + 2, segacc.z);
                    atomicAdd(p + 3, segacc.w);
                }
                cur = bg;
                segacc = v;
            } else {
                segacc.x += v.x; segacc.y += v.y; segacc.z += v.z; segacc.w += v.w;
            }
        }
    }
    if (cur >= 0) {
        float* p = &g_segsum[cur * DD + jg * 4];
        atomicAdd(p + 0, segacc.x);
        atomicAdd(p + 1, segacc.y);
        atomicAdd(p + 2, segacc.z);
        atomicAdd(p + 3, segacc.w);
    }

    sq[slot][jg][0] = q0; sq[slot][jg][1] = q1;
    sq[slot][jg][2] = q2; sq[slot][jg][3] = q3;
    __syncthreads();
    for (int off = 8; off > 0; off >>= 1) {
        if (slot < off) {
#pragma unroll
            for (int m = 0; m < 4; m++) sq[slot][jg][m] += sq[slot + off][jg][m];
        }
        __syncthreads();
    }
    if (slot == 0) {
#pragma unroll
        for (int m = 0; m < 4; m++)
            atomicAdd(&g_stats[jg * 4 + m], sq[0][jg][m]);
    }
}

// ---------------- epilogue: BN params, pooled outputs, fold next W -----------
__global__ void __launch_bounds__(256) k_epi(const float* __restrict__ W,
                                             const float* __restrict__ bnw,
                                             const float* __restrict__ bnb,
                                             float* __restrict__ outp, int layer) {
    __shared__ float ss[DD], sh[DD];
    __shared__ double smean[4][DD];
    int t = threadIdx.x;
    {   // parallel column-sum of segsum over all 256 threads
        int f = t & 63, part = t >> 6;      // 4 partials per feature
        double sum = 0.0;
        for (int g = part; g < NG; g += 4) sum += (double)g_segsum[g * DD + f];
        smean[part][f] = sum;
    }
    __syncthreads();
    if (t < DD) {
        double sum = smean[0][t] + smean[1][t] + smean[2][t] + smean[3][t];
        double n = (double)NN;
        double mean = sum / n;
        double var = g_stats[t] / n - mean * mean;
        float istd = rsqrtf((float)var + BN_EPS);
        float s = istd * bnw[layer * DD + t];
        float shift = bnb[layer * DD + t] - (float)mean * s;
        ss[t] = s; sh[t] = shift;
        g_stats[t] = 0.0;
    }
    __syncthreads();

    for (int idx = t; idx < NG * DD; idx += 256) {
        int g = idx >> 6, j = idx & 63;
        float val = g_segsum[idx] * ss[j] + (float)g_cnt[g] * sh[j];
        g_segsum[idx] = 0.f;
        outp[g * (NL * DD) + layer * DD + j] = val;
        if (layer == NL - 1) outp[NG * NL * DD + g * DD + j] = val;
    }

    if (layer < NL - 1) {
        const float* Wn = W + (layer + 1) * DD * DD;
        for (int idx = t; idx < DD * DD; idx += 256) {
            int j = idx >> 6, k = idx & 63;
            g_Wt[k * DD + j] = ss[k] * Wn[j * DD + k];
        }
        if (t < DD) {
            float c = 0.f;
#pragma unroll
            for (int k = 0; k < DD; k++) c += sh[k] * Wn[t * DD + k];
            g_c[t] = c;
        }
    }
}

// ---------------- driver ----------------
extern "C" void kernel_launch(void* const* d_in, const int* in_sizes, int n_in,
                              void* d_out, int out_size) {
    const float* x     = (const float*)d_in[0];
    const void*  ei    = d_in[1];
    const float* ea    = (const float*)d_in[2];
    const void*  batch = d_in[3];
    const float* W     = (const float*)d_in[4];
    const float* b     = (const float*)d_in[5];
    const float* pa    = (const float*)d_in[6];
    const float* bnw   = (const float*)d_in[7];
    const float* bnb   = (const float*)d_in[8];
    float* outp = (float*)d_out;

    k_prep<<<1, 256>>>(W, ei, batch);
    k_zero_deg<<<(NN + 255) / 256, 256>>>();
    k_hist<<<(NE + 255) / 256, 256>>>(ei);
    k_scan1<<<SCAN_B, 1024>>>();
    k_scan2<<<1, 128>>>();
    k_scan3<<<SCAN_B, 1024>>>();
    k_reorder<<<(NE + 255) / 256, 256>>>(ei, ea);
    for (int L = 0; L < NL; L++) {
        k_lin<<<(NN + 63) / 64, 256>>>(x, L == 0 ? 1 : 0);
        k_gather<<<(NN + 127) / 128, 256>>>(batch, pa, b + L * DD);
        k_epi<<<1, 256>>>(W, bnw, bnb, outp, L);
    }
}

// round 14
// speedup vs baseline: 2.4286x; 1.0275x over previous
#include <cuda_runtime.h>
#include <cuda_fp16.h>

#define NN 100000
#define NE 1000000
#define DD 64
#define NG 128
#define NL 3
#define BN_EPS 1e-5f
#define SCAN_B 98           // ceil(NN/1024)

// ---------------- scratch (device globals; no runtime alloc) ----------------
__device__ __align__(16) __half g_bufA[NN * DD];   // lin output t (fp16 storage)
__device__ __align__(16) float  g_bufB[NN * DD];   // node state g (next layer input)
__device__ double g_stats[DD];                     // per-feature sumsq of g
__device__ __align__(16) float  g_segsum[NG * DD]; // per-graph sums of g
__device__ int    g_cnt[NG];                       // nodes per graph
__device__ float  g_Wt[DD * DD];                   // folded, TRANSPOSED weight
__device__ float  g_c[DD];                         // folded constant
__device__ int    g_idx64;                         // 1 if int64 indices, 0 if int32
// CSR by destination node
__device__ int    g_deg[NN];                       // in-degree histogram
__device__ int    g_rowptr[NN + 1];
__device__ int    g_cursor[NN];
__device__ int    g_part[128];                     // per-block partial sums (SCAN_B used)
__device__ __align__(8) int2 g_edge[NE];           // {src, bitcast(w)} sorted by dst

__device__ __forceinline__ int clampi(int v, int lim) {
    return v < 0 ? 0 : (v >= lim ? lim - 1 : v);
}

__device__ __forceinline__ int ld_idx(const void* p, long long i, int is64, int lim) {
    int v = is64 ? (int)((const long long*)p)[i] : ((const int*)p)[i];
    return clampi(v, lim);
}

// ---------------- prologue: detect dtype, transpose W0, zero, graph counts ---
__global__ void __launch_bounds__(256) k_prep(const float* __restrict__ W,
                                              const void* __restrict__ ei,
                                              const void* __restrict__ batch) {
    int t = threadIdx.x;
    if (t == 0) {
        const int* w1 = (const int*)ei;
        const int* w2 = (const int*)batch;
        int allz = 1;
        for (int i = 1; i < 128; i += 2) allz &= (w1[i] == 0);
        for (int i = 1; i < 128; i += 2) allz &= (w2[i] == 0);
        g_idx64 = allz;
    }
    __syncthreads();
    int is64 = g_idx64;

    for (int idx = t; idx < DD * DD; idx += 256) {
        int j = idx >> 6, k = idx & 63;
        g_Wt[k * DD + j] = W[j * DD + k];          // layer 0: s = 1
    }
    for (int idx = t; idx < DD; idx += 256) { g_c[idx] = 0.f; g_stats[idx] = 0.0; }
    for (int idx = t; idx < NG * DD; idx += 256) g_segsum[idx] = 0.f;
    if (t < NG) {
        int lo = 0, hi = NN;
        while (lo < hi) {
            int m = (lo + hi) >> 1;
            int v = is64 ? (int)((const long long*)batch)[m] : ((const int*)batch)[m];
            if (v < t) lo = m + 1; else hi = m;
        }
        int a = lo;
        lo = 0; hi = NN;
        while (lo < hi) {
            int m = (lo + hi) >> 1;
            int v = is64 ? (int)((const long long*)batch)[m] : ((const int*)batch)[m];
            if (v < t + 1) lo = m + 1; else hi = m;
        }
        g_cnt[t] = lo - a;
    }
}

// ---------------- CSR build ----------------
__global__ void __launch_bounds__(256) k_zero_deg() {
    int i = blockIdx.x * 256 + threadIdx.x;
    if (i < NN) g_deg[i] = 0;
}

__global__ void __launch_bounds__(256) k_hist(const void* __restrict__ ei) {
    int e = blockIdx.x * 256 + threadIdx.x;
    if (e >= NE) return;
    int d = ld_idx(ei, (long long)NE + e, g_idx64, NN);
    atomicAdd(&g_deg[d], 1);
}

// phase 1: per-block sums of g_deg  (grid SCAN_B, block 1024)
__global__ void __launch_bounds__(1024) k_scan1() {
    __shared__ int swarp[32];
    int t = threadIdx.x;
    int i = blockIdx.x * 1024 + t;
    int v = (i < NN) ? g_deg[i] : 0;
    int lane = t & 31, wid = t >> 5;
    int s = v;
#pragma unroll
    for (int off = 16; off > 0; off >>= 1) s += __shfl_down_sync(0xffffffffu, s, off);
    if (lane == 0) swarp[wid] = s;
    __syncthreads();
    if (wid == 0) {
        s = swarp[lane];
#pragma unroll
        for (int off = 16; off > 0; off >>= 1) s += __shfl_down_sync(0xffffffffu, s, off);
        if (lane == 0) g_part[blockIdx.x] = s;
    }
}

// phase 2: exclusive scan of SCAN_B partials (1 block, 128 threads, smem)
__global__ void __launch_bounds__(128) k_scan2() {
    __shared__ int sp[128];
    int t = threadIdx.x;
    int v = (t < SCAN_B) ? g_part[t] : 0;
    sp[t] = v;
    __syncthreads();
    for (int off = 1; off < 128; off <<= 1) {
        int u = (t >= off) ? sp[t - off] : 0;
        __syncthreads();
        sp[t] += u;
        __syncthreads();
    }
    if (t < SCAN_B) g_part[t] = sp[t] - v;         // exclusive
    if (t == 127) g_rowptr[NN] = sp[127];          // total
}

// phase 3: in-block exclusive scan + block offset -> rowptr, cursor
__global__ void __launch_bounds__(1024) k_scan3() {
    __shared__ int swarp[32];
    int t = threadIdx.x;
    int i = blockIdx.x * 1024 + t;
    int v = (i < NN) ? g_deg[i] : 0;
    int lane = t & 31, wid = t >> 5;
    int inc = v;
#pragma unroll
    for (int off = 1; off < 32; off <<= 1) {
        int u = __shfl_up_sync(0xffffffffu, inc, off);
        if (lane >= off) inc += u;
    }
    if (lane == 31) swarp[wid] = inc;
    __syncthreads();
    if (wid == 0) {
        int ws = swarp[lane];
#pragma unroll
        for (int off = 1; off < 32; off <<= 1) {
            int u = __shfl_up_sync(0xffffffffu, ws, off);
            if (lane >= off) ws += u;
        }
        swarp[lane] = ws;
    }
    __syncthreads();
    int warpoff = (wid == 0) ? 0 : swarp[wid - 1];
    int excl = g_part[blockIdx.x] + warpoff + inc - v;
    if (i < NN) {
        g_rowptr[i] = excl;
        g_cursor[i] = excl;
    }
}

__global__ void __launch_bounds__(256) k_reorder(const void* __restrict__ ei,
                                                 const float* __restrict__ ew) {
    int e = blockIdx.x * 256 + threadIdx.x;
    if (e >= NE) return;
    int is64 = g_idx64;
    int s = ld_idx(ei, e, is64, NN);
    int d = ld_idx(ei, (long long)NE + e, is64, NN);
    float w = ew[e];
    int pos = atomicAdd(&g_cursor[d], 1);
    g_edge[pos] = make_int2(s, __float_as_int(w));
}

// ---------------- lin: t = in @ Wt (+c) -> bufA (fp16) -----------------------
__global__ void __launch_bounds__(256) k_lin(const float* __restrict__ xin, int use_ext) {
    __shared__ __align__(16) float sA[64][64];
    __shared__ __align__(16) float sW[64][64];   // sW[k][j]
    int t = threadIdx.x;
    int base = blockIdx.x * 64;

    for (int idx = t; idx < DD * DD; idx += 256) sW[idx >> 6][idx & 63] = g_Wt[idx];
    for (int idx = t; idx < 64 * DD; idx += 256) {
        int r = idx >> 6, k = idx & 63;
        int n = base + r;
        float v = 0.f;
        if (n < NN) v = use_ext ? xin[n * DD + k] : g_bufB[n * DD + k];
        sA[r][k] = v;
    }
    __syncthreads();

    int jg = t & 15;        // feature group (4 feats)
    int ns = (t >> 4) * 4;  // first of 4 node rows

    float4 cv = *(const float4*)&g_c[jg * 4];
    float4 acc0 = cv, acc1 = cv, acc2 = cv, acc3 = cv;

#pragma unroll 8
    for (int k = 0; k < DD; k++) {
        float4 wv = *(const float4*)&sW[k][jg * 4];
        float a0 = sA[ns + 0][k];
        float a1 = sA[ns + 1][k];
        float a2 = sA[ns + 2][k];
        float a3 = sA[ns + 3][k];
        acc0.x += a0 * wv.x; acc0.y += a0 * wv.y; acc0.z += a0 * wv.z; acc0.w += a0 * wv.w;
        acc1.x += a1 * wv.x; acc1.y += a1 * wv.y; acc1.z += a1 * wv.z; acc1.w += a1 * wv.w;
        acc2.x += a2 * wv.x; acc2.y += a2 * wv.y; acc2.z += a2 * wv.z; acc2.w += a2 * wv.w;
        acc3.x += a3 * wv.x; acc3.y += a3 * wv.y; acc3.z += a3 * wv.z; acc3.w += a3 * wv.w;
    }

    float4 accs[4] = {acc0, acc1, acc2, acc3};
#pragma unroll
    for (int i = 0; i < 4; i++) {
        int n = base + ns + i;
        if (n < NN) {
            __half2 h0 = __floats2half2_rn(accs[i].x, accs[i].y);
            __half2 h1 = __floats2half2_rn(accs[i].z, accs[i].w);
            uint2 pk = make_uint2(*(unsigned*)&h0, *(unsigned*)&h1);
            *(uint2*)&g_bufA[n * DD + jg * 4] = pk;
        }
    }
}

// ---------------- gather: agg + bias -> prelu -> g; fused sumsq + segsum -----
// 16 threads/node; group of 16 threads handles 8 CONTIGUOUS nodes (run-length).
// Uniform predicated 4-wide edge loop; fp16 rows converted to fp32 on load.
__device__ __forceinline__ void fma_half4(float4& acc, float w, uint2 pk) {
    __half2 h0 = *(__half2*)&pk.x;
    __half2 h1 = *(__half2*)&pk.y;
    float2 f0 = __half22float2(h0);
    float2 f1 = __half22float2(h1);
    acc.x += w * f0.x; acc.y += w * f0.y; acc.z += w * f1.x; acc.w += w * f1.y;
}

__global__ void __launch_bounds__(256) k_gather(const void* __restrict__ batch,
                                                const float* __restrict__ prelu_a,
                                                const float* __restrict__ bias) {
    __shared__ double sq[16][16][4];   // [slot][jg][q0..3] = 8 KB
    int t = threadIdx.x;
    int jg = t & 15, slot = t >> 4;
    float a = prelu_a[0];
    int base = blockIdx.x * 128 + slot * 8;
    int is64 = g_idx64;
    float4 bv = *(const float4*)&bias[jg * 4];

    double q0 = 0, q1 = 0, q2 = 0, q3 = 0;
    float4 segacc = make_float4(0.f, 0.f, 0.f, 0.f);
    int cur = -1;

#pragma unroll 1
    for (int i = 0; i < 8; i++) {
        int n = base + i;
        if (n < NN) {
            int st = g_rowptr[n], en = g_rowptr[n + 1];   // broadcast
            float4 v = bv;
            float4 va1 = make_float4(0.f, 0.f, 0.f, 0.f);
            float4 va2 = make_float4(0.f, 0.f, 0.f, 0.f);
            float4 va3 = make_float4(0.f, 0.f, 0.f, 0.f);
            int last = en - 1;
#pragma unroll 1
            for (int e = st; e < en; e += 4) {
                int i1 = e + 1 <= last ? e + 1 : last;
                int i2 = e + 2 <= last ? e + 2 : last;
                int i3 = e + 3 <= last ? e + 3 : last;
                int2 e0 = g_edge[e];
                int2 e1 = g_edge[i1];
                int2 e2 = g_edge[i2];
                int2 e3 = g_edge[i3];
                uint2 x0 = *(const uint2*)&g_bufA[e0.x * DD + jg * 4];
                uint2 x1 = *(const uint2*)&g_bufA[e1.x * DD + jg * 4];
                uint2 x2 = *(const uint2*)&g_bufA[e2.x * DD + jg * 4];
                uint2 x3 = *(const uint2*)&g_bufA[e3.x * DD + jg * 4];
                float w0 = __int_as_float(e0.y);
                float w1 = (e + 1 <= last) ? __int_as_float(e1.y) : 0.f;
                float w2 = (e + 2 <= last) ? __int_as_float(e2.y) : 0.f;
                float w3 = (e + 3 <= last) ? __int_as_float(e3.y) : 0.f;
                fma_half4(v,   w0, x0);
                fma_half4(va1, w1, x1);
                fma_half4(va2, w2, x2);
                fma_half4(va3, w3, x3);
            }
            v.x += va1.x + va2.x + va3.x;
            v.y += va1.y + va2.y + va3.y;
            v.z += va1.z + va2.z + va3.z;
            v.w += va1.w + va2.w + va3.w;

            v.x = v.x >= 0.f ? v.x : a * v.x;
            v.y = v.y >= 0.f ? v.y : a * v.y;
            v.z = v.z >= 0.f ? v.z : a * v.z;
            v.w = v.w >= 0.f ? v.w : a * v.w;
            *(float4*)&g_bufB[n * DD + jg * 4] = v;
            q0 += (double)v.x * v.x; q1 += (double)v.y * v.y;
            q2 += (double)v.z * v.z; q3 += (double)v.w * v.w;
            int bg = ld_idx(batch, n, is64, NG);
            if (bg != cur) {
                if (cur >= 0) {
                    float* p = &g_segsum[cur * DD + jg * 4];
                    atomicAdd(p + 0, segacc.x);
                    atomicAdd(p + 1, segacc.y);
                    atomicAdd(p + 2, segacc.z);
                    atomicAdd(p + 3, segacc.w);
                }
                cur = bg;
                segacc = v;
            } else {
                segacc.x += v.x; segacc.y += v.y; segacc.z += v.z; segacc.w += v.w;
            }
        }
    }
    if (cur >= 0) {
        float* p = &g_segsum[cur * DD + jg * 4];
        atomicAdd(p + 0, segacc.x);
        atomicAdd(p + 1, segacc.y);
        atomicAdd(p + 2, segacc.z);
        atomicAdd(p + 3, segacc.w);
    }

    sq[slot][jg][0] = q0; sq[slot][jg][1] = q1;
    sq[slot][jg][2] = q2; sq[slot][jg][3] = q3;
    __syncthreads();
    for (int off = 8; off > 0; off >>= 1) {
        if (slot < off) {
#pragma unroll
            for (int m = 0; m < 4; m++) sq[slot][jg][m] += sq[slot + off][jg][m];
        }
        __syncthreads();
    }
    if (slot == 0) {
#pragma unroll
        for (int m = 0; m < 4; m++)
            atomicAdd(&g_stats[jg * 4 + m], sq[0][jg][m]);
    }
}

// ---------------- epilogue: BN params, pooled outputs, fold next W -----------
__global__ void __launch_bounds__(256) k_epi(const float* __restrict__ W,
                                             const float* __restrict__ bnw,
                                             const float* __restrict__ bnb,
                                             float* __restrict__ outp, int layer) {
    __shared__ float ss[DD], sh[DD];
    __shared__ double smean[4][DD];
    int t = threadIdx.x;
    {   // parallel column-sum of segsum over all 256 threads
        int f = t & 63, part = t >> 6;      // 4 partials per feature
        double sum = 0.0;
        for (int g = part; g < NG; g += 4) sum += (double)g_segsum[g * DD + f];
        smean[part][f] = sum;
    }
    __syncthreads();
    if (t < DD) {
        double sum = smean[0][t] + smean[1][t] + smean[2][t] + smean[3][t];
        double n = (double)NN;
        double mean = sum / n;
        double var = g_stats[t] / n - mean * mean;
        float istd = rsqrtf((float)var + BN_EPS);
        float s = istd * bnw[layer * DD + t];
        float shift = bnb[layer * DD + t] - (float)mean * s;
        ss[t] = s; sh[t] = shift;
        g_stats[t] = 0.0;
    }
    __syncthreads();

    for (int idx = t; idx < NG * DD; idx += 256) {
        int g = idx >> 6, j = idx & 63;
        float val = g_segsum[idx] * ss[j] + (float)g_cnt[g] * sh[j];
        g_segsum[idx] = 0.f;
        outp[g * (NL * DD) + layer * DD + j] = val;
        if (layer == NL - 1) outp[NG * NL * DD + g * DD + j] = val;
    }

    if (layer < NL - 1) {
        const float* Wn = W + (layer + 1) * DD * DD;
        for (int idx = t; idx < DD * DD; idx += 256) {
            int j = idx >> 6, k = idx & 63;
            g_Wt[k * DD + j] = ss[k] * Wn[j * DD + k];
        }
        if (t < DD) {
            float c = 0.f;
#pragma unroll
            for (int k = 0; k < DD; k++) c += sh[k] * Wn[t * DD + k];
            g_c[t] = c;
        }
    }
}

// ---------------- driver ----------------
extern "C" void kernel_launch(void* const* d_in, const int* in_sizes, int n_in,
                              void* d_out, int out_size) {
    const float* x     = (const float*)d_in[0];
    const void*  ei    = d_in[1];
    const float* ea    = (const float*)d_in[2];
    const void*  batch = d_in[3];
    const float* W     = (const float*)d_in[4];
    const float* b     = (const float*)d_in[5];
    const float* pa    = (const float*)d_in[6];
    const float* bnw   = (const float*)d_in[7];
    const float* bnb   = (const float*)d_in[8];
    float* outp = (float*)d_out;

    k_prep<<<1, 256>>>(W, ei, batch);
    k_zero_deg<<<(NN + 255) / 256, 256>>>();
    k_hist<<<(NE + 255) / 256, 256>>>(ei);
    k_scan1<<<SCAN_B, 1024>>>();
    k_scan2<<<1, 128>>>();
    k_scan3<<<SCAN_B, 1024>>>();
    k_reorder<<<(NE + 255) / 256, 256>>>(ei, ea);
    for (int L = 0; L < NL; L++) {
        k_lin<<<(NN + 63) / 64, 256>>>(x, L == 0 ? 1 : 0);
        k_gather<<<(NN + 127) / 128, 256>>>(batch, pa, b + L * DD);
        k_epi<<<1, 256>>>(W, bnw, bnb, outp, L);
    }
}

// round 15
// speedup vs baseline: 2.6624x; 1.0963x over previous
#include <cuda_runtime.h>

#define NN 100000
#define NE 1000000
#define DD 64
#define NG 128
#define NL 3
#define BN_EPS 1e-5f
#define SCAN_B 98           // ceil(NN/1024)

// ---------------- scratch (device globals; no runtime alloc) ----------------
__device__ __align__(16) float  g_bufA[NN * DD];   // node state h (ping)
__device__ __align__(16) float  g_bufB[NN * DD];   // node state h (pong)
__device__ double g_stats[DD];                     // per-feature sumsq of h
__device__ __align__(16) float  g_segsum[NG * DD]; // per-graph sums of h
__device__ int    g_cnt[NG];                       // nodes per graph
__device__ float  g_Wt[DD * DD];                   // folded, TRANSPOSED weight
__device__ float  g_c[DD];                         // folded constant (shift @ W^T)
__device__ int    g_idx64;                         // 1 if int64 indices, 0 if int32
// CSR by destination node
__device__ int    g_deg[NN];
__device__ int    g_rowptr[NN + 1];
__device__ int    g_cursor[NN];
__device__ int    g_part[128];
__device__ __align__(8) int2 g_edge[NE];           // {src, bitcast(w)} sorted by dst

__device__ __forceinline__ int clampi(int v, int lim) {
    return v < 0 ? 0 : (v >= lim ? lim - 1 : v);
}

__device__ __forceinline__ int ld_idx(const void* p, long long i, int is64, int lim) {
    int v = is64 ? (int)((const long long*)p)[i] : ((const int*)p)[i];
    return clampi(v, lim);
}

// ---------------- prologue ----------------
__global__ void __launch_bounds__(256) k_prep(const float* __restrict__ W,
                                              const void* __restrict__ ei,
                                              const void* __restrict__ batch) {
    int t = threadIdx.x;
    if (t == 0) {
        const int* w1 = (const int*)ei;
        const int* w2 = (const int*)batch;
        int allz = 1;
        for (int i = 1; i < 128; i += 2) allz &= (w1[i] == 0);
        for (int i = 1; i < 128; i += 2) allz &= (w2[i] == 0);
        g_idx64 = allz;
    }
    __syncthreads();
    int is64 = g_idx64;

    for (int idx = t; idx < DD * DD; idx += 256) {
        int j = idx >> 6, k = idx & 63;
        g_Wt[k * DD + j] = W[j * DD + k];          // layer 0: s = 1
    }
    for (int idx = t; idx < DD; idx += 256) { g_c[idx] = 0.f; g_stats[idx] = 0.0; }
    for (int idx = t; idx < NG * DD; idx += 256) g_segsum[idx] = 0.f;
    if (t < NG) {
        int lo = 0, hi = NN;
        while (lo < hi) {
            int m = (lo + hi) >> 1;
            int v = is64 ? (int)((const long long*)batch)[m] : ((const int*)batch)[m];
            if (v < t) lo = m + 1; else hi = m;
        }
        int a = lo;
        lo = 0; hi = NN;
        while (lo < hi) {
            int m = (lo + hi) >> 1;
            int v = is64 ? (int)((const long long*)batch)[m] : ((const int*)batch)[m];
            if (v < t + 1) lo = m + 1; else hi = m;
        }
        g_cnt[t] = lo - a;
    }
}

// ---------------- CSR build ----------------
__global__ void __launch_bounds__(256) k_zero_deg() {
    int i = blockIdx.x * 256 + threadIdx.x;
    if (i < NN) g_deg[i] = 0;
}

__global__ void __launch_bounds__(256) k_hist(const void* __restrict__ ei) {
    int e = blockIdx.x * 256 + threadIdx.x;
    if (e >= NE) return;
    int d = ld_idx(ei, (long long)NE + e, g_idx64, NN);
    atomicAdd(&g_deg[d], 1);
}

__global__ void __launch_bounds__(1024) k_scan1() {
    __shared__ int swarp[32];
    int t = threadIdx.x;
    int i = blockIdx.x * 1024 + t;
    int v = (i < NN) ? g_deg[i] : 0;
    int lane = t & 31, wid = t >> 5;
    int s = v;
#pragma unroll
    for (int off = 16; off > 0; off >>= 1) s += __shfl_down_sync(0xffffffffu, s, off);
    if (lane == 0) swarp[wid] = s;
    __syncthreads();
    if (wid == 0) {
        s = swarp[lane];
#pragma unroll
        for (int off = 16; off > 0; off >>= 1) s += __shfl_down_sync(0xffffffffu, s, off);
        if (lane == 0) g_part[blockIdx.x] = s;
    }
}

__global__ void __launch_bounds__(128) k_scan2() {
    __shared__ int sp[128];
    int t = threadIdx.x;
    int v = (t < SCAN_B) ? g_part[t] : 0;
    sp[t] = v;
    __syncthreads();
    for (int off = 1; off < 128; off <<= 1) {
        int u = (t >= off) ? sp[t - off] : 0;
        __syncthreads();
        sp[t] += u;
        __syncthreads();
    }
    if (t < SCAN_B) g_part[t] = sp[t] - v;
    if (t == 127) g_rowptr[NN] = sp[127];
}

__global__ void __launch_bounds__(1024) k_scan3() {
    __shared__ int swarp[32];
    int t = threadIdx.x;
    int i = blockIdx.x * 1024 + t;
    int v = (i < NN) ? g_deg[i] : 0;
    int lane = t & 31, wid = t >> 5;
    int inc = v;
#pragma unroll
    for (int off = 1; off < 32; off <<= 1) {
        int u = __shfl_up_sync(0xffffffffu, inc, off);
        if (lane >= off) inc += u;
    }
    if (lane == 31) swarp[wid] = inc;
    __syncthreads();
    if (wid == 0) {
        int ws = swarp[lane];
#pragma unroll
        for (int off = 1; off < 32; off <<= 1) {
            int u = __shfl_up_sync(0xffffffffu, ws, off);
            if (lane >= off) ws += u;
        }
        swarp[lane] = ws;
    }
    __syncthreads();
    int warpoff = (wid == 0) ? 0 : swarp[wid - 1];
    int excl = g_part[blockIdx.x] + warpoff + inc - v;
    if (i < NN) {
        g_rowptr[i] = excl;
        g_cursor[i] = excl;
    }
}

__global__ void __launch_bounds__(256) k_reorder(const void* __restrict__ ei,
                                                 const float* __restrict__ ew) {
    int e = blockIdx.x * 256 + threadIdx.x;
    if (e >= NE) return;
    int is64 = g_idx64;
    int s = ld_idx(ei, e, is64, NN);
    int d = ld_idx(ei, (long long)NE + e, is64, NN);
    float w = ew[e];
    int pos = atomicAdd(&g_cursor[d], 1);
    g_edge[pos] = make_int2(s, __float_as_int(w));
}

// ---------------- fused layer: gather(prev h or x) -> GEMM -> prelu -> stats -
// 64 nodes/block, 256 threads. Phase1: 16-thread groups gather 4 contiguous
// nodes each into smem (+ weighted degree sw). Phase2: 64x64 GEMM from smem,
// + sw*c + bias, prelu, write h, fused sumsq + run-length segsum.
__global__ void __launch_bounds__(256) k_layer(const float* __restrict__ xin,
                                               int rd_sel, int wr_a,
                                               const void* __restrict__ batch,
                                               const float* __restrict__ prelu_a,
                                               const float* __restrict__ bias) {
    __shared__ __align__(16) float sAgg[64][68];   // padded: conflict-free
    __shared__ __align__(16) float sW[64][64];     // sW[k][j]
    __shared__ float ssw[64];
    __shared__ double sq[16][16][4];
    int t = threadIdx.x;
    int jg = t & 15, slot = t >> 4;
    int base = blockIdx.x * 64;

    for (int idx = t; idx < DD * DD; idx += 256) sW[idx >> 6][idx & 63] = g_Wt[idx];

    const float* rsrc = (rd_sel == 0) ? xin : (rd_sel == 1 ? g_bufA : g_bufB);
    float* wdst = wr_a ? g_bufA : g_bufB;

    // ---- phase 1: gather 4 nodes per slot ----
#pragma unroll 1
    for (int i = 0; i < 4; i++) {
        int n = base + slot * 4 + i;
        float4 v = make_float4(0.f, 0.f, 0.f, 0.f);
        float4 va1 = v, va2 = v, va3 = v;
        float sw = 0.f;
        if (n < NN) {
            int st = g_rowptr[n], en = g_rowptr[n + 1];
            int last = en - 1;
#pragma unroll 1
            for (int e = st; e < en; e += 4) {
                int i1 = e + 1 <= last ? e + 1 : last;
                int i2 = e + 2 <= last ? e + 2 : last;
                int i3 = e + 3 <= last ? e + 3 : last;
                int2 e0 = g_edge[e];
                int2 e1 = g_edge[i1];
                int2 e2 = g_edge[i2];
                int2 e3 = g_edge[i3];
                float4 x0 = *(const float4*)&rsrc[e0.x * DD + jg * 4];
                float4 x1 = *(const float4*)&rsrc[e1.x * DD + jg * 4];
                float4 x2 = *(const float4*)&rsrc[e2.x * DD + jg * 4];
                float4 x3 = *(const float4*)&rsrc[e3.x * DD + jg * 4];
                float w0 = __int_as_float(e0.y);
                float w1 = (e + 1 <= last) ? __int_as_float(e1.y) : 0.f;
                float w2 = (e + 2 <= last) ? __int_as_float(e2.y) : 0.f;
                float w3 = (e + 3 <= last) ? __int_as_float(e3.y) : 0.f;
                v.x   += w0 * x0.x; v.y   += w0 * x0.y; v.z   += w0 * x0.z; v.w   += w0 * x0.w;
                va1.x += w1 * x1.x; va1.y += w1 * x1.y; va1.z += w1 * x1.z; va1.w += w1 * x1.w;
                va2.x += w2 * x2.x; va2.y += w2 * x2.y; va2.z += w2 * x2.z; va2.w += w2 * x2.w;
                va3.x += w3 * x3.x; va3.y += w3 * x3.y; va3.z += w3 * x3.z; va3.w += w3 * x3.w;
                sw += w0 + w1 + w2 + w3;
            }
        }
        v.x += va1.x + va2.x + va3.x;
        v.y += va1.y + va2.y + va3.y;
        v.z += va1.z + va2.z + va3.z;
        v.w += va1.w + va2.w + va3.w;
        *(float4*)&sAgg[slot * 4 + i][jg * 4] = v;
        if (jg == 0) ssw[slot * 4 + i] = sw;
    }
    __syncthreads();

    // ---- phase 2: GEMM + epilogue ----
    float a = prelu_a[0];
    int is64 = g_idx64;
    float4 cv = *(const float4*)&g_c[jg * 4];
    float4 bv = *(const float4*)&bias[jg * 4];
    int ns = slot * 4;

    float4 acc0 = make_float4(0.f, 0.f, 0.f, 0.f);
    float4 acc1 = acc0, acc2 = acc0, acc3 = acc0;
#pragma unroll 8
    for (int k = 0; k < DD; k++) {
        float4 wv = *(const float4*)&sW[k][jg * 4];
        float a0 = sAgg[ns + 0][k];
        float a1 = sAgg[ns + 1][k];
        float a2 = sAgg[ns + 2][k];
        float a3 = sAgg[ns + 3][k];
        acc0.x += a0 * wv.x; acc0.y += a0 * wv.y; acc0.z += a0 * wv.z; acc0.w += a0 * wv.w;
        acc1.x += a1 * wv.x; acc1.y += a1 * wv.y; acc1.z += a1 * wv.z; acc1.w += a1 * wv.w;
        acc2.x += a2 * wv.x; acc2.y += a2 * wv.y; acc2.z += a2 * wv.z; acc2.w += a2 * wv.w;
        acc3.x += a3 * wv.x; acc3.y += a3 * wv.y; acc3.z += a3 * wv.z; acc3.w += a3 * wv.w;
    }

    double q0 = 0, q1 = 0, q2 = 0, q3 = 0;
    float4 segacc = make_float4(0.f, 0.f, 0.f, 0.f);
    int cur = -1;
    float4 accs[4] = {acc0, acc1, acc2, acc3};
#pragma unroll
    for (int i = 0; i < 4; i++) {
        int n = base + ns + i;
        if (n < NN) {
            float swn = ssw[ns + i];
            float4 v = accs[i];
            v.x += swn * cv.x + bv.x;
            v.y += swn * cv.y + bv.y;
            v.z += swn * cv.z + bv.z;
            v.w += swn * cv.w + bv.w;
            v.x = v.x >= 0.f ? v.x : a * v.x;
            v.y = v.y >= 0.f ? v.y : a * v.y;
            v.z = v.z >= 0.f ? v.z : a * v.z;
            v.w = v.w >= 0.f ? v.w : a * v.w;
            *(float4*)&wdst[n * DD + jg * 4] = v;
            q0 += (double)v.x * v.x; q1 += (double)v.y * v.y;
            q2 += (double)v.z * v.z; q3 += (double)v.w * v.w;
            int bg = ld_idx(batch, n, is64, NG);
            if (bg != cur) {
                if (cur >= 0) {
                    float* p = &g_segsum[cur * DD + jg * 4];
                    atomicAdd(p + 0, segacc.x);
                    atomicAdd(p + 1, segacc.y);
                    atomicAdd(p + 2, segacc.z);
                    atomicAdd(p + 3, segacc.w);
                }
                cur = bg;
                segacc = v;
            } else {
                segacc.x += v.x; segacc.y += v.y; segacc.z += v.z; segacc.w += v.w;
            }
        }
    }
    if (cur >= 0) {
        float* p = &g_segsum[cur * DD + jg * 4];
        atomicAdd(p + 0, segacc.x);
        atomicAdd(p + 1, segacc.y);
        atomicAdd(p + 2, segacc.z);
        atomicAdd(p + 3, segacc.w);
    }

    sq[slot][jg][0] = q0; sq[slot][jg][1] = q1;
    sq[slot][jg][2] = q2; sq[slot][jg][3] = q3;
    __syncthreads();
    for (int off = 8; off > 0; off >>= 1) {
        if (slot < off) {
#pragma unroll
            for (int m = 0; m < 4; m++) sq[slot][jg][m] += sq[slot + off][jg][m];
        }
        __syncthreads();
    }
    if (slot == 0) {
#pragma unroll
        for (int m = 0; m < 4; m++)
            atomicAdd(&g_stats[jg * 4 + m], sq[0][jg][m]);
    }
}

// ---------------- epilogue: BN params, pooled outputs, fold next W -----------
__global__ void __launch_bounds__(256) k_epi(const float* __restrict__ W,
                                             const float* __restrict__ bnw,
                                             const float* __restrict__ bnb,
                                             float* __restrict__ outp, int layer) {
    __shared__ float ss[DD], sh[DD];
    __shared__ double smean[4][DD];
    int t = threadIdx.x;
    {
        int f = t & 63, part = t >> 6;
        double sum = 0.0;
        for (int g = part; g < NG; g += 4) sum += (double)g_segsum[g * DD + f];
        smean[part][f] = sum;
    }
    __syncthreads();
    if (t < DD) {
        double sum = smean[0][t] + smean[1][t] + smean[2][t] + smean[3][t];
        double n = (double)NN;
        double mean = sum / n;
        double var = g_stats[t] / n - mean * mean;
        float istd = rsqrtf((float)var + BN_EPS);
        float s = istd * bnw[layer * DD + t];
        float shift = bnb[layer * DD + t] - (float)mean * s;
        ss[t] = s; sh[t] = shift;
        g_stats[t] = 0.0;
    }
    __syncthreads();

    for (int idx = t; idx < NG * DD; idx += 256) {
        int g = idx >> 6, j = idx & 63;
        float val = g_segsum[idx] * ss[j] + (float)g_cnt[g] * sh[j];
        g_segsum[idx] = 0.f;
        outp[g * (NL * DD) + layer * DD + j] = val;
        if (layer == NL - 1) outp[NG * NL * DD + g * DD + j] = val;
    }

    if (layer < NL - 1) {
        const float* Wn = W + (layer + 1) * DD * DD;
        for (int idx = t; idx < DD * DD; idx += 256) {
            int j = idx >> 6, k = idx & 63;
            g_Wt[k * DD + j] = ss[k] * Wn[j * DD + k];
        }
        if (t < DD) {
            float c = 0.f;
#pragma unroll
            for (int k = 0; k < DD; k++) c += sh[k] * Wn[t * DD + k];
            g_c[t] = c;
        }
    }
}

// ---------------- driver ----------------
extern "C" void kernel_launch(void* const* d_in, const int* in_sizes, int n_in,
                              void* d_out, int out_size) {
    const float* x     = (const float*)d_in[0];
    const void*  ei    = d_in[1];
    const float* ea    = (const float*)d_in[2];
    const void*  batch = d_in[3];
    const float* W     = (const float*)d_in[4];
    const float* b     = (const float*)d_in[5];
    const float* pa    = (const float*)d_in[6];
    const float* bnw   = (const float*)d_in[7];
    const float* bnb   = (const float*)d_in[8];
    float* outp = (float*)d_out;

    k_prep<<<1, 256>>>(W, ei, batch);
    k_zero_deg<<<(NN + 255) / 256, 256>>>();
    k_hist<<<(NE + 255) / 256, 256>>>(ei);
    k_scan1<<<SCAN_B, 1024>>>();
    k_scan2<<<1, 128>>>();
    k_scan3<<<SCAN_B, 1024>>>();
    k_reorder<<<(NE + 255) / 256, 256>>>(ei, ea);
    // layers: L0 reads x -> bufA; L1 bufA -> bufB; L2 bufB -> bufA
    for (int L = 0; L < NL; L++) {
        int rd_sel = (L == 0) ? 0 : ((L == 1) ? 1 : 2);
        int wr_a = (L != 1) ? 1 : 0;
        k_layer<<<(NN + 63) / 64, 256>>>(x, rd_sel, wr_a, batch, pa, b + L * DD);
        k_epi<<<1, 256>>>(W, bnw, bnb, outp, L);
    }
}

// round 17
// speedup vs baseline: 2.6951x; 1.0123x over previous
#include <cuda_runtime.h>

#define NN 100000
#define NE 1000000
#define DD 64
#define NG 128
#define NL 3
#define BN_EPS 1e-5f
#define SCAN_B 98           // ceil(NN/1024)

// ---------------- scratch (device globals; no runtime alloc) ----------------
__device__ __align__(16) float  g_bufA[NN * DD];   // node state h (ping)
__device__ __align__(16) float  g_bufB[NN * DD];   // node state h (pong)
__device__ double g_stats[DD];                     // per-feature sumsq of h
__device__ __align__(16) float  g_segsum[NG * DD]; // per-graph sums of h
__device__ int    g_cnt[NG];                       // nodes per graph
__device__ float  g_Wt[DD * DD];                   // folded, TRANSPOSED weight
__device__ float  g_c[DD];                         // folded constant (shift @ W^T)
__device__ int    g_idx64;                         // 1 if int64 indices, 0 if int32
// CSR by destination node
__device__ int    g_deg[NN];
__device__ int    g_rowptr[NN + 1];
__device__ int    g_cursor[NN];
__device__ int    g_part[128];
__device__ __align__(8) int2 g_edge[NE];           // {src, bitcast(w)} sorted by dst

__device__ __forceinline__ int clampi(int v, int lim) {
    return v < 0 ? 0 : (v >= lim ? lim - 1 : v);
}

__device__ __forceinline__ int ld_idx(const void* p, long long i, int is64, int lim) {
    int v = is64 ? (int)((const long long*)p)[i] : ((const int*)p)[i];
    return clampi(v, lim);
}

// ---------------- prologue ----------------
__global__ void __launch_bounds__(256) k_prep(const float* __restrict__ W,
                                              const void* __restrict__ ei,
                                              const void* __restrict__ batch) {
    int t = threadIdx.x;
    if (t == 0) {
        const int* w1 = (const int*)ei;
        const int* w2 = (const int*)batch;
        int allz = 1;
        for (int i = 1; i < 128; i += 2) allz &= (w1[i] == 0);
        for (int i = 1; i < 128; i += 2) allz &= (w2[i] == 0);
        g_idx64 = allz;
    }
    __syncthreads();
    int is64 = g_idx64;

    for (int idx = t; idx < DD * DD; idx += 256) {
        int j = idx >> 6, k = idx & 63;
        g_Wt[k * DD + j] = W[j * DD + k];          // layer 0: s = 1
    }
    for (int idx = t; idx < DD; idx += 256) { g_c[idx] = 0.f; g_stats[idx] = 0.0; }
    for (int idx = t; idx < NG * DD; idx += 256) g_segsum[idx] = 0.f;
    if (t < NG) {
        int lo = 0, hi = NN;
        while (lo < hi) {
            int m = (lo + hi) >> 1;
            int v = is64 ? (int)((const long long*)batch)[m] : ((const int*)batch)[m];
            if (v < t) lo = m + 1; else hi = m;
        }
        int a = lo;
        lo = 0; hi = NN;
        while (lo < hi) {
            int m = (lo + hi) >> 1;
            int v = is64 ? (int)((const long long*)batch)[m] : ((const int*)batch)[m];
            if (v < t + 1) lo = m + 1; else hi = m;
        }
        g_cnt[t] = lo - a;
    }
}

// ---------------- CSR build ----------------
__global__ void __launch_bounds__(256) k_zero_deg() {
    int i = blockIdx.x * 256 + threadIdx.x;
    if (i < NN) g_deg[i] = 0;
}

__global__ void __launch_bounds__(256) k_hist(const void* __restrict__ ei) {
    int e = blockIdx.x * 256 + threadIdx.x;
    if (e >= NE) return;
    int d = ld_idx(ei, (long long)NE + e, g_idx64, NN);
    atomicAdd(&g_deg[d], 1);
}

__global__ void __launch_bounds__(1024) k_scan1() {
    __shared__ int swarp[32];
    int t = threadIdx.x;
    int i = blockIdx.x * 1024 + t;
    int v = (i < NN) ? g_deg[i] : 0;
    int lane = t & 31, wid = t >> 5;
    int s = v;
#pragma unroll
    for (int off = 16; off > 0; off >>= 1) s += __shfl_down_sync(0xffffffffu, s, off);
    if (lane == 0) swarp[wid] = s;
    __syncthreads();
    if (wid == 0) {
        s = swarp[lane];
#pragma unroll
        for (int off = 16; off > 0; off >>= 1) s += __shfl_down_sync(0xffffffffu, s, off);
        if (lane == 0) g_part[blockIdx.x] = s;
    }
}

__global__ void __launch_bounds__(128) k_scan2() {
    __shared__ int sp[128];
    int t = threadIdx.x;
    int v = (t < SCAN_B) ? g_part[t] : 0;
    sp[t] = v;
    __syncthreads();
    for (int off = 1; off < 128; off <<= 1) {
        int u = (t >= off) ? sp[t - off] : 0;
        __syncthreads();
        sp[t] += u;
        __syncthreads();
    }
    if (t < SCAN_B) g_part[t] = sp[t] - v;
    if (t == 127) g_rowptr[NN] = sp[127];
}

__global__ void __launch_bounds__(1024) k_scan3() {
    __shared__ int swarp[32];
    int t = threadIdx.x;
    int i = blockIdx.x * 1024 + t;
    int v = (i < NN) ? g_deg[i] : 0;
    int lane = t & 31, wid = t >> 5;
    int inc = v;
#pragma unroll
    for (int off = 1; off < 32; off <<= 1) {
        int u = __shfl_up_sync(0xffffffffu, inc, off);
        if (lane >= off) inc += u;
    }
    if (lane == 31) swarp[wid] = inc;
    __syncthreads();
    if (wid == 0) {
        int ws = swarp[lane];
#pragma unroll
        for (int off = 1; off < 32; off <<= 1) {
            int u = __shfl_up_sync(0xffffffffu, ws, off);
            if (lane >= off) ws += u;
        }
        swarp[lane] = ws;
    }
    __syncthreads();
    int warpoff = (wid == 0) ? 0 : swarp[wid - 1];
    int excl = g_part[blockIdx.x] + warpoff + inc - v;
    if (i < NN) {
        g_rowptr[i] = excl;
        g_cursor[i] = excl;
    }
}

__global__ void __launch_bounds__(256) k_reorder(const void* __restrict__ ei,
                                                 const float* __restrict__ ew) {
    int e = blockIdx.x * 256 + threadIdx.x;
    if (e >= NE) return;
    int is64 = g_idx64;
    int s = ld_idx(ei, e, is64, NN);
    int d = ld_idx(ei, (long long)NE + e, is64, NN);
    float w = ew[e];
    int pos = atomicAdd(&g_cursor[d], 1);
    g_edge[pos] = make_int2(s, __float_as_int(w));
}

// ---------------- fused layer: gather(prev h or x) -> GEMM -> prelu -> stats -
__global__ void __launch_bounds__(256) k_layer(const float* __restrict__ xin,
                                               int rd_sel, int wr_a,
                                               const void* __restrict__ batch,
                                               const float* __restrict__ prelu_a,
                                               const float* __restrict__ bias) {
    __shared__ __align__(16) float sAgg[64][68];   // padded: 16B-aligned rows
    __shared__ __align__(16) float sW[64][64];     // sW[k][j]
    __shared__ float ssw[64];
    __shared__ double sq[16][16][4];
    int t = threadIdx.x;
    int jg = t & 15, slot = t >> 4;
    int base = blockIdx.x * 64;

    for (int idx = t; idx < DD * DD; idx += 256) sW[idx >> 6][idx & 63] = g_Wt[idx];

    const float* rsrc = (rd_sel == 0) ? xin : (rd_sel == 1 ? g_bufA : g_bufB);
    float* wdst = wr_a ? g_bufA : g_bufB;

    // ---- phase 1: gather 4 nodes per slot ----
#pragma unroll 1
    for (int i = 0; i < 4; i++) {
        int n = base + slot * 4 + i;
        float4 v = make_float4(0.f, 0.f, 0.f, 0.f);
        float4 va1 = v, va2 = v, va3 = v;
        float sw = 0.f;
        if (n < NN) {
            int st = g_rowptr[n], en = g_rowptr[n + 1];
            int last = en - 1;
#pragma unroll 1
            for (int e = st; e < en; e += 4) {
                int i1 = e + 1 <= last ? e + 1 : last;
                int i2 = e + 2 <= last ? e + 2 : last;
                int i3 = e + 3 <= last ? e + 3 : last;
                int2 e0 = g_edge[e];
                int2 e1 = g_edge[i1];
                int2 e2 = g_edge[i2];
                int2 e3 = g_edge[i3];
                float4 x0 = *(const float4*)&rsrc[e0.x * DD + jg * 4];
                float4 x1 = *(const float4*)&rsrc[e1.x * DD + jg * 4];
                float4 x2 = *(const float4*)&rsrc[e2.x * DD + jg * 4];
                float4 x3 = *(const float4*)&rsrc[e3.x * DD + jg * 4];
                float w0 = __int_as_float(e0.y);
                float w1 = (e + 1 <= last) ? __int_as_float(e1.y) : 0.f;
                float w2 = (e + 2 <= last) ? __int_as_float(e2.y) : 0.f;
                float w3 = (e + 3 <= last) ? __int_as_float(e3.y) : 0.f;
                v.x   += w0 * x0.x; v.y   += w0 * x0.y; v.z   += w0 * x0.z; v.w   += w0 * x0.w;
                va1.x += w1 * x1.x; va1.y += w1 * x1.y; va1.z += w1 * x1.z; va1.w += w1 * x1.w;
                va2.x += w2 * x2.x; va2.y += w2 * x2.y; va2.z += w2 * x2.z; va2.w += w2 * x2.w;
                va3.x += w3 * x3.x; va3.y += w3 * x3.y; va3.z += w3 * x3.z; va3.w += w3 * x3.w;
                sw += w0 + w1 + w2 + w3;
            }
        }
        v.x += va1.x + va2.x + va3.x;
        v.y += va1.y + va2.y + va3.y;
        v.z += va1.z + va2.z + va3.z;
        v.w += va1.w + va2.w + va3.w;
        *(float4*)&sAgg[slot * 4 + i][jg * 4] = v;
        if (jg == 0) ssw[slot * 4 + i] = sw;
    }
    __syncthreads();

    // ---- phase 2: GEMM (k-steps of 4, float4 A loads) + epilogue ----
    float a = prelu_a[0];
    int is64 = g_idx64;
    float4 cv = *(const float4*)&g_c[jg * 4];
    float4 bv = *(const float4*)&bias[jg * 4];
    int ns = slot * 4;

    float4 acc0 = make_float4(0.f, 0.f, 0.f, 0.f);
    float4 acc1 = acc0, acc2 = acc0, acc3 = acc0;
#pragma unroll 4
    for (int k = 0; k < DD; k += 4) {
        float4 w0 = *(const float4*)&sW[k + 0][jg * 4];
        float4 w1 = *(const float4*)&sW[k + 1][jg * 4];
        float4 w2 = *(const float4*)&sW[k + 2][jg * 4];
        float4 w3 = *(const float4*)&sW[k + 3][jg * 4];
        float4 a0 = *(const float4*)&sAgg[ns + 0][k];
        float4 a1 = *(const float4*)&sAgg[ns + 1][k];
        float4 a2 = *(const float4*)&sAgg[ns + 2][k];
        float4 a3 = *(const float4*)&sAgg[ns + 3][k];

        acc0.x += a0.x * w0.x; acc0.y += a0.x * w0.y; acc0.z += a0.x * w0.z; acc0.w += a0.x * w0.w;
        acc0.x += a0.y * w1.x; acc0.y += a0.y * w1.y; acc0.z += a0.y * w1.z; acc0.w += a0.y * w1.w;
        acc0.x += a0.z * w2.x; acc0.y += a0.z * w2.y; acc0.z += a0.z * w2.z; acc0.w += a0.z * w2.w;
        acc0.x += a0.w * w3.x; acc0.y += a0.w * w3.y; acc0.z += a0.w * w3.z; acc0.w += a0.w * w3.w;

        acc1.x += a1.x * w0.x; acc1.y += a1.x * w0.y; acc1.z += a1.x * w0.z; acc1.w += a1.x * w0.w;
        acc1.x += a1.y * w1.x; acc1.y += a1.y * w1.y; acc1.z += a1.y * w1.z; acc1.w += a1.y * w1.w;
        acc1.x += a1.z * w2.x; acc1.y += a1.z * w2.y; acc1.z += a1.z * w2.z; acc1.w += a1.z * w2.w;
        acc1.x += a1.w * w3.x; acc1.y += a1.w * w3.y; acc1.z += a1.w * w3.z; acc1.w += a1.w * w3.w;

        acc2.x += a2.x * w0.x; acc2.y += a2.x * w0.y; acc2.z += a2.x * w0.z; acc2.w += a2.x * w0.w;
        acc2.x += a2.y * w1.x; acc2.y += a2.y * w1.y; acc2.z += a2.y * w1.z; acc2.w += a2.y * w1.w;
        acc2.x += a2.z * w2.x; acc2.y += a2.z * w2.y; acc2.z += a2.z * w2.z; acc2.w += a2.z * w2.w;
        acc2.x += a2.w * w3.x; acc2.y += a2.w * w3.y; acc2.z += a2.w * w3.z; acc2.w += a2.w * w3.w;

        acc3.x += a3.x * w0.x; acc3.y += a3.x * w0.y; acc3.z += a3.x * w0.z; acc3.w += a3.x * w0.w;
        acc3.x += a3.y * w1.x; acc3.y += a3.y * w1.y; acc3.z += a3.y * w1.z; acc3.w += a3.y * w1.w;
        acc3.x += a3.z * w2.x; acc3.y += a3.z * w2.y; acc3.z += a3.z * w2.z; acc3.w += a3.z * w2.w;
        acc3.x += a3.w * w3.x; acc3.y += a3.w * w3.y; acc3.z += a3.w * w3.z; acc3.w += a3.w * w3.w;
    }

    double q0 = 0, q1 = 0, q2 = 0, q3 = 0;
    float4 segacc = make_float4(0.f, 0.f, 0.f, 0.f);
    int cur = -1;
    float4 accs[4] = {acc0, acc1, acc2, acc3};
#pragma unroll
    for (int i = 0; i < 4; i++) {
        int n = base + ns + i;
        if (n < NN) {
            float swn = ssw[ns + i];
            float4 v = accs[i];
            v.x += swn * cv.x + bv.x;
            v.y += swn * cv.y + bv.y;
            v.z += swn * cv.z + bv.z;
            v.w += swn * cv.w + bv.w;
            v.x = v.x >= 0.f ? v.x : a * v.x;
            v.y = v.y >= 0.f ? v.y : a * v.y;
            v.z = v.z >= 0.f ? v.z : a * v.z;
            v.w = v.w >= 0.f ? v.w : a * v.w;
            *(float4*)&wdst[n * DD + jg * 4] = v;
            q0 += (double)v.x * v.x; q1 += (double)v.y * v.y;
            q2 += (double)v.z * v.z; q3 += (double)v.w * v.w;
            int bg = ld_idx(batch, n, is64, NG);
            if (bg != cur) {
                if (cur >= 0) {
                    float* p = &g_segsum[cur * DD + jg * 4];
                    atomicAdd(p + 0, segacc.x);
                    atomicAdd(p + 1, segacc.y);
                    atomicAdd(p + 2, segacc.z);
                    atomicAdd(p + 3, segacc.w);
                }
                cur = bg;
                segacc = v;
            } else {
                segacc.x += v.x; segacc.y += v.y; segacc.z += v.z; segacc.w += v.w;
            }
        }
    }
    if (cur >= 0) {
        float* p = &g_segsum[cur * DD + jg * 4];
        atomicAdd(p + 0, segacc.x);
        atomicAdd(p + 1, segacc.y);
        atomicAdd(p + 2, segacc.z);
        atomicAdd(p + 3, segacc.w);
    }

    sq[slot][jg][0] = q0; sq[slot][jg][1] = q1;
    sq[slot][jg][2] = q2; sq[slot][jg][3] = q3;
    __syncthreads();
    for (int off = 8; off > 0; off >>= 1) {
        if (slot < off) {
#pragma unroll
            for (int m = 0; m < 4; m++) sq[slot][jg][m] += sq[slot + off][jg][m];
        }
        __syncthreads();
    }
    if (slot == 0) {
#pragma unroll
        for (int m = 0; m < 4; m++)
            atomicAdd(&g_stats[jg * 4 + m], sq[0][jg][m]);
    }
}

// ---------------- epilogue: BN params, pooled outputs, fold next W -----------
__global__ void __launch_bounds__(256) k_epi(const float* __restrict__ W,
                                             const float* __restrict__ bnw,
                                             const float* __restrict__ bnb,
                                             float* __restrict__ outp, int layer) {
    __shared__ float ss[DD], sh[DD];
    __shared__ double smean[4][DD];
    int t = threadIdx.x;
    {
        int f = t & 63, part = t >> 6;
        double sum = 0.0;
        for (int g = part; g < NG; g += 4) sum += (double)g_segsum[g * DD + f];
        smean[part][f] = sum;
    }
    __syncthreads();
    if (t < DD) {
        double sum = smean[0][t] + smean[1][t] + smean[2][t] + smean[3][t];
        double n = (double)NN;
        double mean = sum / n;
        double var = g_stats[t] / n - mean * mean;
        float istd = rsqrtf((float)var + BN_EPS);
        float s = istd * bnw[layer * DD + t];
        float shift = bnb[layer * DD + t] - (float)mean * s;
        ss[t] = s; sh[t] = shift;
        g_stats[t] = 0.0;
    }
    __syncthreads();

    for (int idx = t; idx < NG * DD; idx += 256) {
        int g = idx >> 6, j = idx & 63;
        float val = g_segsum[idx] * ss[j] + (float)g_cnt[g] * sh[j];
        g_segsum[idx] = 0.f;
        outp[g * (NL * DD) + layer * DD + j] = val;
        if (layer == NL - 1) outp[NG * NL * DD + g * DD + j] = val;
    }

    if (layer < NL - 1) {
        const float* Wn = W + (layer + 1) * DD * DD;
        for (int idx = t; idx < DD * DD; idx += 256) {
            int j = idx >> 6, k = idx & 63;
            g_Wt[k * DD + j] = ss[k] * Wn[j * DD + k];
        }
        if (t < DD) {
            float c = 0.f;
#pragma unroll
            for (int k = 0; k < DD; k++) c += sh[k] * Wn[t * DD + k];
            g_c[t] = c;
        }
    }
}

// ---------------- driver ----------------
extern "C" void kernel_launch(void* const* d_in, const int* in_sizes, int n_in,
                              void* d_out, int out_size) {
    const float* x     = (const float*)d_in[0];
    const void*  ei    = d_in[1];
    const float* ea    = (const float*)d_in[2];
    const void*  batch = d_in[3];
    const float* W     = (const float*)d_in[4];
    const float* b     = (const float*)d_in[5];
    const float* pa    = (const float*)d_in[6];
    const float* bnw   = (const float*)d_in[7];
    const float* bnb   = (const float*)d_in[8];
    float* outp = (float*)d_out;

    k_prep<<<1, 256>>>(W, ei, batch);
    k_zero_deg<<<(NN + 255) / 256, 256>>>();
    k_hist<<<(NE + 255) / 256, 256>>>(ei);
    k_scan1<<<SCAN_B, 1024>>>();
    k_scan2<<<1, 128>>>();
    k_scan3<<<SCAN_B, 1024>>>();
    k_reorder<<<(NE + 255) / 256, 256>>>(ei, ea);
    // layers: L0 reads x -> bufA; L1 bufA -> bufB; L2 bufB -> bufA
    for (int L = 0; L < NL; L++) {
        int rd_sel = (L == 0) ? 0 : ((L == 1) ? 1 : 2);
        int wr_a = (L != 1) ? 1 : 0;
        k_layer<<<(NN + 63) / 64, 256>>>(x, rd_sel, wr_a, batch, pa, b + L * DD);
        k_epi<<<1, 256>>>(W, bnw, bnb, outp, L);
    }
}